// round 1
// baseline (speedup 1.0000x reference)
#include <cuda_runtime.h>
#include <math.h>

// ---------------------------------------------------------------------------
// Problem constants (GlmAsrEncoderAttention): B=4, S=2048, HID=2048,
// NH=16, NKV=4, HD=128. qkv width = 2048 + 512 + 512 = 3072.
// ---------------------------------------------------------------------------
#define B_    4
#define S_    2048
#define HID_  2048
#define NH_   16
#define NKV_  4
#define HD_   128
#define QSZ   (NH_ * HD_)          // 2048
#define KVSZ  (NKV_ * HD_)         // 512
#define QKVN  (QSZ + 2 * KVSZ)     // 3072
#define TOK   (B_ * S_)            // 8192

// Scratch (no cudaMalloc allowed): qkv projection output + attention output.
__device__ float g_qkv[(size_t)TOK * QKVN];   // ~100.7 MB
__device__ float g_attn[(size_t)TOK * HID_];  // ~67.1 MB

// ---------------------------------------------------------------------------
// SGEMM with bias: C[M,N] = A[M,K] @ B[K,N] + bias[N]
// BM=BN=128, BK=16, 256 threads, 8x8 per thread with 16-strided reg tiling
// (cols tx+16j / rows ty+16i) => conflict-free Bs reads, broadcast As reads.
// Requires M%128==0, N%128==0, K%16==0 (true for all our shapes).
// ---------------------------------------------------------------------------
__global__ __launch_bounds__(256) void sgemm_bias_kernel(
    const float* __restrict__ A, const float* __restrict__ Bm,
    const float* __restrict__ bias, float* __restrict__ C,
    int M, int N, int K)
{
    const int BM = 128, BN = 128, BK = 16;
    __shared__ float As[BK][BM + 4];   // transposed A tile, pad 4 -> 2-way max
    __shared__ float Bs[BK][BN];

    int tid = threadIdx.x;
    int tx = tid & 15;
    int ty = tid >> 4;
    int m0 = blockIdx.y * BM;
    int n0 = blockIdx.x * BN;

    float acc[8][8];
#pragma unroll
    for (int i = 0; i < 8; i++)
#pragma unroll
        for (int j = 0; j < 8; j++) acc[i][j] = 0.f;

    int ar  = tid >> 2;   // 0..63  (A tile row, +64 on 2nd pass)
    int ac4 = tid & 3;    // 0..3   (A tile float4 col)
    int br  = tid >> 5;   // 0..7   (B tile row, +8 on 2nd pass)
    int bc4 = tid & 31;   // 0..31  (B tile float4 col)

    for (int k0 = 0; k0 < K; k0 += BK) {
#pragma unroll
        for (int p = 0; p < 2; p++) {
            int r = ar + p * 64;
            float4 v = *reinterpret_cast<const float4*>(
                &A[(size_t)(m0 + r) * K + k0 + 4 * ac4]);
            As[4 * ac4 + 0][r] = v.x;
            As[4 * ac4 + 1][r] = v.y;
            As[4 * ac4 + 2][r] = v.z;
            As[4 * ac4 + 3][r] = v.w;
        }
#pragma unroll
        for (int p = 0; p < 2; p++) {
            int r = br + p * 8;
            float4 v = *reinterpret_cast<const float4*>(
                &Bm[(size_t)(k0 + r) * N + n0 + 4 * bc4]);
            *reinterpret_cast<float4*>(&Bs[r][4 * bc4]) = v;
        }
        __syncthreads();

#pragma unroll
        for (int k = 0; k < BK; k++) {
            float a[8], b[8];
#pragma unroll
            for (int i = 0; i < 8; i++) a[i] = As[k][ty + 16 * i];
#pragma unroll
            for (int j = 0; j < 8; j++) b[j] = Bs[k][tx + 16 * j];
#pragma unroll
            for (int i = 0; i < 8; i++)
#pragma unroll
                for (int j = 0; j < 8; j++)
                    acc[i][j] = fmaf(a[i], b[j], acc[i][j]);
        }
        __syncthreads();
    }

#pragma unroll
    for (int j = 0; j < 8; j++) {
        float bj = bias[n0 + tx + 16 * j];
#pragma unroll
        for (int i = 0; i < 8; i++) {
            C[(size_t)(m0 + ty + 16 * i) * N + n0 + tx + 16 * j] = acc[i][j] + bj;
        }
    }
}

// ---------------------------------------------------------------------------
// RoPE applied in-place to q (16 heads) and k (4 heads) portions of g_qkv.
// One thread handles one (token, head, pair d / d+64).
// ---------------------------------------------------------------------------
__global__ __launch_bounds__(256) void rope_kernel(
    float* __restrict__ qkv,
    const float* __restrict__ cosb, const float* __restrict__ sinb)
{
    int idx = blockIdx.x * blockDim.x + threadIdx.x;  // tok*20*64 total
    int d    = idx & 63;
    int head = (idx >> 6) % (NH_ + NKV_);
    int tok  = idx / (64 * (NH_ + NKV_));
    if (tok >= TOK) return;
    int s = tok & (S_ - 1);

    int off = (head < NH_) ? head * HD_ : QSZ + (head - NH_) * HD_;
    float* row = qkv + (size_t)tok * QKVN + off;

    float c  = cosb[s * 64 + d];
    float sn = sinb[s * 64 + d];
    float x1 = row[d];
    float x2 = row[d + 64];
    row[d]      = x1 * c - x2 * sn;
    row[d + 64] = x2 * c + x1 * sn;
}

// ---------------------------------------------------------------------------
// Flash-style attention (no mask). Block = one (b, h, 64-query tile).
// 256 threads as (ty 0..15, tx 0..15): each thread owns rows 4ty+i and
// cols tx+16j (j<4 for scores over 64 keys, j<8 for 128 output dims).
// Q/K stored k-major (transposed) in smem so inner reads are broadcast /
// consecutive (conflict-free). Online softmax, warp-half shfl reductions.
// ---------------------------------------------------------------------------
#define QT 64
#define KT 64
#define ATTN_SMEM_FLOATS (2 * 128 * (QT + 1) + KT * HD_ + QT * 68)
#define ATTN_SMEM_BYTES  (ATTN_SMEM_FLOATS * 4)

__global__ __launch_bounds__(256) void attn_kernel(
    const float* __restrict__ qkv, float* __restrict__ out)
{
    extern __shared__ float smem[];
    float (*Qs)[QT + 1] = (float (*)[QT + 1])(smem);                    // [128][65]
    float (*Ks)[KT + 1] = (float (*)[KT + 1])(smem + 128 * (QT + 1));   // [128][65]
    float (*Vs)[HD_]    = (float (*)[HD_])(smem + 2 * 128 * (QT + 1));  // [64][128]
    float (*Ss)[68]     = (float (*)[68])(smem + 2 * 128 * (QT + 1) + KT * HD_);

    int qt = blockIdx.x;
    int h  = blockIdx.y;
    int b  = blockIdx.z;
    int kvh = h >> 2;             // GQA: 4 q-heads per kv-head (repeat semantics)
    int tid = threadIdx.x;
    int tx = tid & 15;
    int ty = tid >> 4;

    const float scale = 0.08838834764831845f;  // 1/sqrt(128)

    size_t tok0 = (size_t)b * S_;
    const float* qbase  = qkv + (tok0 + (size_t)qt * QT) * QKVN + h * HD_;
    const float* kbase0 = qkv + tok0 * QKVN + QSZ + kvh * HD_;
    const float* vbase0 = qkv + tok0 * QKVN + QSZ + KVSZ + kvh * HD_;

    // Load Q tile transposed: Qs[d][r]
    {
        int r0 = tid >> 5;   // 0..7
        int c  = tid & 31;   // float4 col (d/4)
#pragma unroll
        for (int p = 0; p < QT / 8; p++) {
            int r = r0 + p * 8;
            float4 v = *reinterpret_cast<const float4*>(&qbase[(size_t)r * QKVN + 4 * c]);
            Qs[4 * c + 0][r] = v.x;
            Qs[4 * c + 1][r] = v.y;
            Qs[4 * c + 2][r] = v.z;
            Qs[4 * c + 3][r] = v.w;
        }
    }

    float m_run[4], l_run[4], o_acc[4][8];
#pragma unroll
    for (int i = 0; i < 4; i++) {
        m_run[i] = -1e30f;
        l_run[i] = 0.f;
#pragma unroll
        for (int j = 0; j < 8; j++) o_acc[i][j] = 0.f;
    }

    for (int kt = 0; kt < S_ / KT; kt++) {
        __syncthreads();  // previous tile's consumers done (also covers Q load)

        const float* kb = kbase0 + (size_t)kt * KT * QKVN;
        const float* vb = vbase0 + (size_t)kt * KT * QKVN;
        int r0 = tid >> 5;
        int c  = tid & 31;
#pragma unroll
        for (int p = 0; p < KT / 8; p++) {
            int r = r0 + p * 8;
            float4 v = *reinterpret_cast<const float4*>(&kb[(size_t)r * QKVN + 4 * c]);
            Ks[4 * c + 0][r] = v.x;
            Ks[4 * c + 1][r] = v.y;
            Ks[4 * c + 2][r] = v.z;
            Ks[4 * c + 3][r] = v.w;
            float4 w = *reinterpret_cast<const float4*>(&vb[(size_t)r * QKVN + 4 * c]);
            *reinterpret_cast<float4*>(&Vs[r][4 * c]) = w;
        }
        __syncthreads();

        // Scores: sc[i][j] = Q(row 4ty+i) . K(col tx+16j)
        float sc[4][4];
#pragma unroll
        for (int i = 0; i < 4; i++)
#pragma unroll
            for (int j = 0; j < 4; j++) sc[i][j] = 0.f;

        for (int kk = 0; kk < HD_; kk++) {
            float a[4], bb[4];
#pragma unroll
            for (int i = 0; i < 4; i++) a[i] = Qs[kk][4 * ty + i];
#pragma unroll
            for (int j = 0; j < 4; j++) bb[j] = Ks[kk][tx + 16 * j];
#pragma unroll
            for (int i = 0; i < 4; i++)
#pragma unroll
                for (int j = 0; j < 4; j++)
                    sc[i][j] = fmaf(a[i], bb[j], sc[i][j]);
        }

        // Online softmax per query row (row owned by one 16-lane half-warp)
#pragma unroll
        for (int i = 0; i < 4; i++) {
            float mx = -1e30f;
#pragma unroll
            for (int j = 0; j < 4; j++) {
                sc[i][j] *= scale;
                mx = fmaxf(mx, sc[i][j]);
            }
#pragma unroll
            for (int o = 1; o < 16; o <<= 1)
                mx = fmaxf(mx, __shfl_xor_sync(0xffffffffu, mx, o));
            float m_new = fmaxf(m_run[i], mx);
            float alpha = __expf(m_run[i] - m_new);
            float lsum = 0.f;
#pragma unroll
            for (int j = 0; j < 4; j++) {
                float p = __expf(sc[i][j] - m_new);
                Ss[4 * ty + i][tx + 16 * j] = p;
                lsum += p;
            }
#pragma unroll
            for (int o = 1; o < 16; o <<= 1)
                lsum += __shfl_xor_sync(0xffffffffu, lsum, o);
            l_run[i] = l_run[i] * alpha + lsum;
            m_run[i] = m_new;
#pragma unroll
            for (int j = 0; j < 8; j++) o_acc[i][j] *= alpha;
        }
        __syncwarp();  // Ss row 4ty+i written & read only by this half-warp

        // PV: o += P(64x64) @ V(64x128)
        for (int kk = 0; kk < KT; kk++) {
            float p0 = Ss[4 * ty + 0][kk];
            float p1 = Ss[4 * ty + 1][kk];
            float p2 = Ss[4 * ty + 2][kk];
            float p3 = Ss[4 * ty + 3][kk];
#pragma unroll
            for (int j = 0; j < 8; j++) {
                float v = Vs[kk][tx + 16 * j];
                o_acc[0][j] = fmaf(p0, v, o_acc[0][j]);
                o_acc[1][j] = fmaf(p1, v, o_acc[1][j]);
                o_acc[2][j] = fmaf(p2, v, o_acc[2][j]);
                o_acc[3][j] = fmaf(p3, v, o_acc[3][j]);
            }
        }
    }

    // Epilogue: normalize and write [tok][h*128 + d]
#pragma unroll
    for (int i = 0; i < 4; i++) {
        float inv = 1.f / l_run[i];
        size_t row = ((size_t)b * S_ + (size_t)qt * QT + 4 * ty + i) * HID_ + h * HD_;
#pragma unroll
        for (int j = 0; j < 8; j++)
            out[row + tx + 16 * j] = o_acc[i][j] * inv;
    }
}

// ---------------------------------------------------------------------------
// kernel_launch: QKV GEMM -> RoPE -> attention -> output GEMM.
// All launches on the default stream (serialized, graph-capturable).
// ---------------------------------------------------------------------------
extern "C" void kernel_launch(void* const* d_in, const int* in_sizes, int n_in,
                              void* d_out, int out_size)
{
    // Resolve inputs by element count (robust to ordering; cos precedes sin).
    const float *hidden = nullptr, *cosb = nullptr, *sinb = nullptr;
    const float *wqkv = nullptr, *bqkv = nullptr, *wo = nullptr, *bo = nullptr;
    for (int i = 0; i < n_in; i++) {
        long sz = in_sizes[i];
        const float* p = (const float*)d_in[i];
        if (sz == (long)TOK * HID_)            hidden = p;      // 16777216
        else if (sz == (long)S_ * 64) {                          // 131072 (x2)
            if (!cosb) cosb = p; else sinb = p;
        }
        else if (sz == (long)HID_ * QKVN)      wqkv = p;        // 6291456
        else if (sz == (long)QKVN)             bqkv = p;        // 3072
        else if (sz == (long)HID_ * HID_)      wo = p;          // 4194304
        else if (sz == (long)HID_)             bo = p;          // 2048
    }
    float* out = (float*)d_out;

    float *qkv = nullptr, *attn = nullptr;
    cudaGetSymbolAddress((void**)&qkv, g_qkv);
    cudaGetSymbolAddress((void**)&attn, g_attn);

    // 1) QKV projection: [8192,2048] @ [2048,3072] + b
    {
        dim3 grid(QKVN / 128, TOK / 128);  // (24, 64)
        sgemm_bias_kernel<<<grid, 256>>>(hidden, wqkv, bqkv, qkv, TOK, QKVN, HID_);
    }

    // 2) RoPE in-place on q and k heads
    {
        int total = TOK * (NH_ + NKV_) * 64;
        rope_kernel<<<total / 256, 256>>>(qkv, cosb, sinb);
    }

    // 3) Attention
    {
        cudaFuncSetAttribute(attn_kernel,
                             cudaFuncAttributeMaxDynamicSharedMemorySize,
                             ATTN_SMEM_BYTES);
        dim3 grid(S_ / QT, NH_, B_);  // (32, 16, 4)
        attn_kernel<<<grid, 256, ATTN_SMEM_BYTES>>>(qkv, attn);
    }

    // 4) Output projection: [8192,2048] @ [2048,2048] + b
    {
        dim3 grid(HID_ / 128, TOK / 128);  // (16, 64)
        sgemm_bias_kernel<<<grid, 256>>>(attn, wo, bo, out, TOK, HID_, HID_);
    }
}

// round 3
// speedup vs baseline: 1.3618x; 1.3618x over previous
#include <cuda_runtime.h>
#include <cuda_bf16.h>
#include <cstdint>
#include <math.h>

// ---------------------------------------------------------------------------
// Problem constants: B=4, S=2048, HID=2048, NH=16, NKV=4, HD=128.
// ---------------------------------------------------------------------------
#define B_    4
#define S_    2048
#define HID_  2048
#define NH_   16
#define NKV_  4
#define HD_   128
#define QSZ   (NH_ * HD_)          // 2048
#define KVSZ  (NKV_ * HD_)         // 512
#define QKVN  (QSZ + 2 * KVSZ)     // 3072
#define TOK   (B_ * S_)            // 8192

__device__ float g_qkv[(size_t)TOK * QKVN];
__device__ float g_attn[(size_t)TOK * HID_];

// ---------------------------------------------------------------------------
// Helpers (base sm_103-safe: ldmatrix + mma.sync only, NO tcgen05)
// ---------------------------------------------------------------------------
__device__ __forceinline__ uint32_t smem_u32(const void* p) {
    uint32_t a;
    asm("{ .reg .u64 t; cvta.to.shared.u64 t, %1; cvt.u32.u64 %0, t; }"
        : "=r"(a) : "l"(p));
    return a;
}
__device__ __forceinline__ void ldsm_x4(uint32_t addr, uint32_t& r0, uint32_t& r1,
                                        uint32_t& r2, uint32_t& r3) {
    asm volatile("ldmatrix.sync.aligned.m8n8.x4.shared.b16 {%0,%1,%2,%3}, [%4];"
                 : "=r"(r0), "=r"(r1), "=r"(r2), "=r"(r3) : "r"(addr));
}
__device__ __forceinline__ void mma_bf16(float* d, const uint32_t* a,
                                         const uint32_t* b) {
    asm volatile(
        "mma.sync.aligned.m16n8k16.row.col.f32.bf16.bf16.f32 "
        "{%0,%1,%2,%3}, {%4,%5,%6,%7}, {%8,%9}, {%0,%1,%2,%3};"
        : "+f"(d[0]), "+f"(d[1]), "+f"(d[2]), "+f"(d[3])
        : "r"(a[0]), "r"(a[1]), "r"(a[2]), "r"(a[3]), "r"(b[0]), "r"(b[1]));
}
__device__ __forceinline__ uint32_t pk(__nv_bfloat16 a, __nv_bfloat16 b) {
    __nv_bfloat162 t = __halves2bfloat162(a, b);
    return *reinterpret_cast<uint32_t*>(&t);
}
// swizzled byte offset inside a [rows][64 bf16] tile (128B rows, XOR-16B)
__device__ __forceinline__ uint32_t swz(uint32_t row, uint32_t kbyte) {
    return (row * 128 + kbyte) ^ ((row & 7) << 4);
}

// ---------------------------------------------------------------------------
// bf16x3 mma.sync GEMM: C[M,N] = A[M,K] @ B[K,N] + bias[N], fp32 in/out.
// fp32 -> bf16 hi+lo; D += Ah*Bh + Ah*Bl + Al*Bh (fp32 accum in registers).
// Tile 128x128, K-chunk 64, double-buffered bf16 SMEM, 256 thr (8 warps 4Mx2N).
// ---------------------------------------------------------------------------
#define GKC     64
#define STG_B   65536
#define SOFF_AH 0
#define SOFF_AL 16384
#define SOFF_BH 32768
#define SOFF_BL 49152
#define GEMM_SMEM (2 * STG_B)

__global__ __launch_bounds__(256, 1) void gemm3x_kernel(
    const float* __restrict__ A, const float* __restrict__ Bm,
    const float* __restrict__ bias, float* __restrict__ C,
    int M, int N, int K)
{
    extern __shared__ char smem[];
    const uint32_t sbase = smem_u32(smem);
    const int tid = threadIdx.x;
    const int wid = tid >> 5, lane = tid & 31;
    const int m0 = blockIdx.y * 128, n0 = blockIdx.x * 128;
    const int wm = wid & 3;    // warp M index (32 rows each)
    const int wn = wid >> 2;   // warp N index (64 cols each)

    // Producer mappings (identical to proven R1 data layout)
    const int ak4 = tid & 15;                      // A: k-float4 (k = 4*ak4)
    const int am0 = tid >> 4;                      // A: m base (m = am0 + 16*i)
    const int kb  = 4 * (wid & 3) + (lane >> 3);   // B: k block 0..15
    const int n4b = (lane & 7) + 8 * (wid >> 2);   // B: n-float4 base 0..15

    float acc[2][8][4];
#pragma unroll
    for (int i = 0; i < 2; i++)
#pragma unroll
        for (int j = 0; j < 8; j++)
#pragma unroll
            for (int q = 0; q < 4; q++) acc[i][j][q] = 0.f;

    const int NC = K / GKC;
    const float* Arow = A + (size_t)m0 * K;

    float4 av[8];
    float4 bv[2][4];

    // ---- prologue: LDG chunk 0 ----
#pragma unroll
    for (int i = 0; i < 8; i++)
        av[i] = *(const float4*)&Arow[(size_t)(am0 + 16 * i) * K + 4 * ak4];
#pragma unroll
    for (int bi = 0; bi < 2; bi++)
#pragma unroll
        for (int r = 0; r < 4; r++)
            bv[bi][r] = *(const float4*)&Bm[(size_t)(4 * kb + r) * N + n0 +
                                            4 * (n4b + 16 * bi)];

    // ldmatrix per-lane addresses (row part varies by lane; kbyte added later)
    const int a_row = wm * 32 + (lane & 15);          // + ti*16
    const int a_kh  = (lane >> 4) << 4;               // khalf*8 elems = 16 bytes
    const int b_row = wn * 64 + ((lane >> 4) << 3) + (lane & 7);  // + tjj*8
    const int b_kh  = ((lane >> 3) & 1) << 4;

    for (int c = 0; c < NC; c++) {
        const int buf = c & 1;
        char* st = smem + buf * STG_B;

        // ---- split + store chunk c (bf16 hi/lo, swizzled) ----
#pragma unroll
        for (int i = 0; i < 8; i++) {
            int m = am0 + 16 * i;
            uint32_t off = swz(m, 8 * ak4);
            float x0 = av[i].x, x1 = av[i].y, x2 = av[i].z, x3 = av[i].w;
            __nv_bfloat16 h0 = __float2bfloat16(x0), h1 = __float2bfloat16(x1);
            __nv_bfloat16 h2 = __float2bfloat16(x2), h3 = __float2bfloat16(x3);
            uint2 hv, lv;
            hv.x = pk(h0, h1); hv.y = pk(h2, h3);
            lv.x = pk(__float2bfloat16(x0 - __bfloat162float(h0)),
                      __float2bfloat16(x1 - __bfloat162float(h1)));
            lv.y = pk(__float2bfloat16(x2 - __bfloat162float(h2)),
                      __float2bfloat16(x3 - __bfloat162float(h3)));
            *(uint2*)(st + SOFF_AH + off) = hv;
            *(uint2*)(st + SOFF_AL + off) = lv;
        }
#pragma unroll
        for (int bi = 0; bi < 2; bi++) {
            int n4 = n4b + 16 * bi;
            float vr[4][4];
#pragma unroll
            for (int r = 0; r < 4; r++) {
                vr[r][0] = bv[bi][r].x; vr[r][1] = bv[bi][r].y;
                vr[r][2] = bv[bi][r].z; vr[r][3] = bv[bi][r].w;
            }
#pragma unroll
            for (int j = 0; j < 4; j++) {
                uint32_t off = swz(4 * n4 + j, 8 * kb);
                float x0 = vr[0][j], x1 = vr[1][j], x2 = vr[2][j], x3 = vr[3][j];
                __nv_bfloat16 h0 = __float2bfloat16(x0), h1 = __float2bfloat16(x1);
                __nv_bfloat16 h2 = __float2bfloat16(x2), h3 = __float2bfloat16(x3);
                uint2 hv, lv;
                hv.x = pk(h0, h1); hv.y = pk(h2, h3);
                lv.x = pk(__float2bfloat16(x0 - __bfloat162float(h0)),
                          __float2bfloat16(x1 - __bfloat162float(h1)));
                lv.y = pk(__float2bfloat16(x2 - __bfloat162float(h2)),
                          __float2bfloat16(x3 - __bfloat162float(h3)));
                *(uint2*)(st + SOFF_BH + off) = hv;
                *(uint2*)(st + SOFF_BL + off) = lv;
            }
        }
        __syncthreads();

        // ---- LDG chunk c+1 (latency hidden behind MMA below) ----
        if (c + 1 < NC) {
            int kc = (c + 1) * GKC;
#pragma unroll
            for (int i = 0; i < 8; i++)
                av[i] = *(const float4*)&Arow[(size_t)(am0 + 16 * i) * K + kc +
                                              4 * ak4];
#pragma unroll
            for (int bi = 0; bi < 2; bi++)
#pragma unroll
                for (int r = 0; r < 4; r++)
                    bv[bi][r] = *(const float4*)&Bm[(size_t)(kc + 4 * kb + r) * N +
                                                    n0 + 4 * (n4b + 16 * bi)];
        }

        // ---- compute chunk: 4 k16-steps x (AhBh + AhBl + AlBh) ----
        const uint32_t sb = sbase + buf * STG_B;
#pragma unroll
        for (int s = 0; s < 4; s++) {
            const uint32_t kbyte = 32 * s;
            uint32_t ah[2][4], al[2][4];
#pragma unroll
            for (int ti = 0; ti < 2; ti++) {
                uint32_t ra = swz(a_row + 16 * ti, kbyte + a_kh);
                ldsm_x4(sb + SOFF_AH + ra, ah[ti][0], ah[ti][1], ah[ti][2], ah[ti][3]);
                ldsm_x4(sb + SOFF_AL + ra, al[ti][0], al[ti][1], al[ti][2], al[ti][3]);
            }
#pragma unroll
            for (int pj = 0; pj < 4; pj++) {
                uint32_t rb = swz(b_row + 16 * pj, kbyte + b_kh);
                uint32_t bh[4], bl[4];
                ldsm_x4(sb + SOFF_BH + rb, bh[0], bh[1], bh[2], bh[3]);
                ldsm_x4(sb + SOFF_BL + rb, bl[0], bl[1], bl[2], bl[3]);
#pragma unroll
                for (int ti = 0; ti < 2; ti++) {
                    mma_bf16(acc[ti][2 * pj + 0], ah[ti], bh + 0);
                    mma_bf16(acc[ti][2 * pj + 1], ah[ti], bh + 2);
                    mma_bf16(acc[ti][2 * pj + 0], ah[ti], bl + 0);
                    mma_bf16(acc[ti][2 * pj + 1], ah[ti], bl + 2);
                    mma_bf16(acc[ti][2 * pj + 0], al[ti], bh + 0);
                    mma_bf16(acc[ti][2 * pj + 1], al[ti], bh + 2);
                }
            }
        }
        __syncthreads();
    }

    // ---- epilogue: registers -> GMEM with bias (float2 stores) ----
#pragma unroll
    for (int tj = 0; tj < 8; tj++) {
        int col = n0 + wn * 64 + tj * 8 + 2 * (lane & 3);
        float2 bb = *(const float2*)&bias[col];
#pragma unroll
        for (int ti = 0; ti < 2; ti++) {
            int row = m0 + wm * 32 + ti * 16 + (lane >> 2);
            float2 v0, v1;
            v0.x = acc[ti][tj][0] + bb.x; v0.y = acc[ti][tj][1] + bb.y;
            v1.x = acc[ti][tj][2] + bb.x; v1.y = acc[ti][tj][3] + bb.y;
            *(float2*)&C[(size_t)row * N + col] = v0;
            *(float2*)&C[(size_t)(row + 8) * N + col] = v1;
        }
    }
}

// ---------------------------------------------------------------------------
// RoPE (unchanged)
// ---------------------------------------------------------------------------
__global__ __launch_bounds__(256) void rope_kernel(
    float* __restrict__ qkv,
    const float* __restrict__ cosb, const float* __restrict__ sinb)
{
    int idx = blockIdx.x * blockDim.x + threadIdx.x;
    int d    = idx & 63;
    int head = (idx >> 6) % (NH_ + NKV_);
    int tok  = idx / (64 * (NH_ + NKV_));
    if (tok >= TOK) return;
    int s = tok & (S_ - 1);

    int off = (head < NH_) ? head * HD_ : QSZ + (head - NH_) * HD_;
    float* row = qkv + (size_t)tok * QKVN + off;

    float c  = cosb[s * 64 + d];
    float sn = sinb[s * 64 + d];
    float x1 = row[d];
    float x2 = row[d + 64];
    row[d]      = x1 * c - x2 * sn;
    row[d + 64] = x2 * c + x1 * sn;
}

// ---------------------------------------------------------------------------
// Flash-style fp32 attention (unchanged from passing R1)
// ---------------------------------------------------------------------------
#define QT 64
#define KT 64
#define ATTN_SMEM_FLOATS (2 * 128 * (QT + 1) + KT * HD_ + QT * 68)
#define ATTN_SMEM_BYTES  (ATTN_SMEM_FLOATS * 4)

__global__ __launch_bounds__(256) void attn_kernel(
    const float* __restrict__ qkv, float* __restrict__ out)
{
    extern __shared__ float fsm[];
    float (*Qs)[QT + 1] = (float (*)[QT + 1])(fsm);
    float (*Ks)[KT + 1] = (float (*)[KT + 1])(fsm + 128 * (QT + 1));
    float (*Vs)[HD_]    = (float (*)[HD_])(fsm + 2 * 128 * (QT + 1));
    float (*Ss)[68]     = (float (*)[68])(fsm + 2 * 128 * (QT + 1) + KT * HD_);

    int qt = blockIdx.x;
    int h  = blockIdx.y;
    int b  = blockIdx.z;
    int kvh = h >> 2;
    int tid = threadIdx.x;
    int tx = tid & 15;
    int ty = tid >> 4;

    const float scale = 0.08838834764831845f;

    size_t tok0 = (size_t)b * S_;
    const float* qbase  = qkv + (tok0 + (size_t)qt * QT) * QKVN + h * HD_;
    const float* kbase0 = qkv + tok0 * QKVN + QSZ + kvh * HD_;
    const float* vbase0 = qkv + tok0 * QKVN + QSZ + KVSZ + kvh * HD_;

    {
        int r0 = tid >> 5;
        int c  = tid & 31;
#pragma unroll
        for (int p = 0; p < QT / 8; p++) {
            int r = r0 + p * 8;
            float4 v = *reinterpret_cast<const float4*>(&qbase[(size_t)r * QKVN + 4 * c]);
            Qs[4 * c + 0][r] = v.x;
            Qs[4 * c + 1][r] = v.y;
            Qs[4 * c + 2][r] = v.z;
            Qs[4 * c + 3][r] = v.w;
        }
    }

    float m_run[4], l_run[4], o_acc[4][8];
#pragma unroll
    for (int i = 0; i < 4; i++) {
        m_run[i] = -1e30f;
        l_run[i] = 0.f;
#pragma unroll
        for (int j = 0; j < 8; j++) o_acc[i][j] = 0.f;
    }

    for (int kt = 0; kt < S_ / KT; kt++) {
        __syncthreads();

        const float* kb = kbase0 + (size_t)kt * KT * QKVN;
        const float* vb = vbase0 + (size_t)kt * KT * QKVN;
        int r0 = tid >> 5;
        int c  = tid & 31;
#pragma unroll
        for (int p = 0; p < KT / 8; p++) {
            int r = r0 + p * 8;
            float4 v = *reinterpret_cast<const float4*>(&kb[(size_t)r * QKVN + 4 * c]);
            Ks[4 * c + 0][r] = v.x;
            Ks[4 * c + 1][r] = v.y;
            Ks[4 * c + 2][r] = v.z;
            Ks[4 * c + 3][r] = v.w;
            float4 w = *reinterpret_cast<const float4*>(&vb[(size_t)r * QKVN + 4 * c]);
            *reinterpret_cast<float4*>(&Vs[r][4 * c]) = w;
        }
        __syncthreads();

        float sc[4][4];
#pragma unroll
        for (int i = 0; i < 4; i++)
#pragma unroll
            for (int j = 0; j < 4; j++) sc[i][j] = 0.f;

        for (int kk = 0; kk < HD_; kk++) {
            float a[4], bb[4];
#pragma unroll
            for (int i = 0; i < 4; i++) a[i] = Qs[kk][4 * ty + i];
#pragma unroll
            for (int j = 0; j < 4; j++) bb[j] = Ks[kk][tx + 16 * j];
#pragma unroll
            for (int i = 0; i < 4; i++)
#pragma unroll
                for (int j = 0; j < 4; j++)
                    sc[i][j] = fmaf(a[i], bb[j], sc[i][j]);
        }

#pragma unroll
        for (int i = 0; i < 4; i++) {
            float mx = -1e30f;
#pragma unroll
            for (int j = 0; j < 4; j++) {
                sc[i][j] *= scale;
                mx = fmaxf(mx, sc[i][j]);
            }
#pragma unroll
            for (int o = 1; o < 16; o <<= 1)
                mx = fmaxf(mx, __shfl_xor_sync(0xffffffffu, mx, o));
            float m_new = fmaxf(m_run[i], mx);
            float alpha = __expf(m_run[i] - m_new);
            float lsum = 0.f;
#pragma unroll
            for (int j = 0; j < 4; j++) {
                float p = __expf(sc[i][j] - m_new);
                Ss[4 * ty + i][tx + 16 * j] = p;
                lsum += p;
            }
#pragma unroll
            for (int o = 1; o < 16; o <<= 1)
                lsum += __shfl_xor_sync(0xffffffffu, lsum, o);
            l_run[i] = l_run[i] * alpha + lsum;
            m_run[i] = m_new;
#pragma unroll
            for (int j = 0; j < 8; j++) o_acc[i][j] *= alpha;
        }
        __syncwarp();

        for (int kk = 0; kk < KT; kk++) {
            float p0 = Ss[4 * ty + 0][kk];
            float p1 = Ss[4 * ty + 1][kk];
            float p2 = Ss[4 * ty + 2][kk];
            float p3 = Ss[4 * ty + 3][kk];
#pragma unroll
            for (int j = 0; j < 8; j++) {
                float v = Vs[kk][tx + 16 * j];
                o_acc[0][j] = fmaf(p0, v, o_acc[0][j]);
                o_acc[1][j] = fmaf(p1, v, o_acc[1][j]);
                o_acc[2][j] = fmaf(p2, v, o_acc[2][j]);
                o_acc[3][j] = fmaf(p3, v, o_acc[3][j]);
            }
        }
    }

#pragma unroll
    for (int i = 0; i < 4; i++) {
        float inv = 1.f / l_run[i];
        size_t row = ((size_t)b * S_ + (size_t)qt * QT + 4 * ty + i) * HID_ + h * HD_;
#pragma unroll
        for (int j = 0; j < 8; j++)
            out[row + tx + 16 * j] = o_acc[i][j] * inv;
    }
}

// ---------------------------------------------------------------------------
// kernel_launch
// ---------------------------------------------------------------------------
extern "C" void kernel_launch(void* const* d_in, const int* in_sizes, int n_in,
                              void* d_out, int out_size)
{
    const float *hidden = nullptr, *cosb = nullptr, *sinb = nullptr;
    const float *wqkv = nullptr, *bqkv = nullptr, *wo = nullptr, *bo = nullptr;
    for (int i = 0; i < n_in; i++) {
        long sz = in_sizes[i];
        const float* p = (const float*)d_in[i];
        if (sz == (long)TOK * HID_)            hidden = p;
        else if (sz == (long)S_ * 64) {
            if (!cosb) cosb = p; else sinb = p;
        }
        else if (sz == (long)HID_ * QKVN)      wqkv = p;
        else if (sz == (long)QKVN)             bqkv = p;
        else if (sz == (long)HID_ * HID_)      wo = p;
        else if (sz == (long)HID_)             bo = p;
    }
    float* out = (float*)d_out;

    float *qkv = nullptr, *attn = nullptr;
    cudaGetSymbolAddress((void**)&qkv, g_qkv);
    cudaGetSymbolAddress((void**)&attn, g_attn);

    cudaFuncSetAttribute(gemm3x_kernel,
                         cudaFuncAttributeMaxDynamicSharedMemorySize, GEMM_SMEM);
    cudaFuncSetAttribute(attn_kernel,
                         cudaFuncAttributeMaxDynamicSharedMemorySize, ATTN_SMEM_BYTES);

    // 1) QKV projection: [8192,2048] @ [2048,3072] + b
    {
        dim3 grid(QKVN / 128, TOK / 128);  // (24, 64)
        gemm3x_kernel<<<grid, 256, GEMM_SMEM>>>(hidden, wqkv, bqkv, qkv,
                                                TOK, QKVN, HID_);
    }
    // 2) RoPE
    {
        int total = TOK * (NH_ + NKV_) * 64;
        rope_kernel<<<total / 256, 256>>>(qkv, cosb, sinb);
    }
    // 3) Attention
    {
        dim3 grid(S_ / QT, NH_, B_);  // (32, 16, 4)
        attn_kernel<<<grid, 256, ATTN_SMEM_BYTES>>>(qkv, attn);
    }
    // 4) Output projection: [8192,2048] @ [2048,2048] + b
    {
        dim3 grid(HID_ / 128, TOK / 128);  // (16, 64)
        gemm3x_kernel<<<grid, 256, GEMM_SMEM>>>(attn, wo, bo, out,
                                                TOK, HID_, HID_);
    }
}

// round 4
// speedup vs baseline: 3.0993x; 2.2759x over previous
#include <cuda_runtime.h>
#include <cuda_bf16.h>
#include <cstdint>
#include <math.h>

// ---------------------------------------------------------------------------
// Problem constants: B=4, S=2048, HID=2048, NH=16, NKV=4, HD=128.
// ---------------------------------------------------------------------------
#define B_    4
#define S_    2048
#define HID_  2048
#define NH_   16
#define NKV_  4
#define HD_   128
#define QSZ   (NH_ * HD_)          // 2048
#define KVSZ  (NKV_ * HD_)         // 512
#define QKVN  (QSZ + 2 * KVSZ)     // 3072
#define TOK   (B_ * S_)            // 8192

__device__ float g_qkv[(size_t)TOK * QKVN];
__device__ float g_attn[(size_t)TOK * HID_];

// ---------------------------------------------------------------------------
// Helpers (base sm_103-safe: ldmatrix + mma.sync only)
// ---------------------------------------------------------------------------
__device__ __forceinline__ uint32_t smem_u32(const void* p) {
    uint32_t a;
    asm("{ .reg .u64 t; cvta.to.shared.u64 t, %1; cvt.u32.u64 %0, t; }"
        : "=r"(a) : "l"(p));
    return a;
}
__device__ __forceinline__ void ldsm_x4(uint32_t addr, uint32_t& r0, uint32_t& r1,
                                        uint32_t& r2, uint32_t& r3) {
    asm volatile("ldmatrix.sync.aligned.m8n8.x4.shared.b16 {%0,%1,%2,%3}, [%4];"
                 : "=r"(r0), "=r"(r1), "=r"(r2), "=r"(r3) : "r"(addr));
}
__device__ __forceinline__ void mma_bf16(float* d, const uint32_t* a,
                                         const uint32_t* b) {
    asm volatile(
        "mma.sync.aligned.m16n8k16.row.col.f32.bf16.bf16.f32 "
        "{%0,%1,%2,%3}, {%4,%5,%6,%7}, {%8,%9}, {%0,%1,%2,%3};"
        : "+f"(d[0]), "+f"(d[1]), "+f"(d[2]), "+f"(d[3])
        : "r"(a[0]), "r"(a[1]), "r"(a[2]), "r"(a[3]), "r"(b[0]), "r"(b[1]));
}
__device__ __forceinline__ uint32_t pk(__nv_bfloat16 a, __nv_bfloat16 b) {
    __nv_bfloat162 t = __halves2bfloat162(a, b);
    return *reinterpret_cast<uint32_t*>(&t);
}
// swizzled byte offset, 128-byte rows (64 bf16)
__device__ __forceinline__ uint32_t swz(uint32_t row, uint32_t kbyte) {
    return (row * 128 + kbyte) ^ ((row & 7) << 4);
}
// swizzled byte offset, 256-byte rows (128 bf16)
__device__ __forceinline__ uint32_t swz256(uint32_t row, uint32_t kbyte) {
    return (row * 256 + kbyte) ^ ((row & 7) << 4);
}

// ---------------------------------------------------------------------------
// bf16x3 mma.sync GEMM (unchanged from passing R3)
// ---------------------------------------------------------------------------
#define GKC     64
#define STG_B   65536
#define SOFF_AH 0
#define SOFF_AL 16384
#define SOFF_BH 32768
#define SOFF_BL 49152
#define GEMM_SMEM (2 * STG_B)

__global__ __launch_bounds__(256, 1) void gemm3x_kernel(
    const float* __restrict__ A, const float* __restrict__ Bm,
    const float* __restrict__ bias, float* __restrict__ C,
    int M, int N, int K)
{
    extern __shared__ char smem[];
    const uint32_t sbase = smem_u32(smem);
    const int tid = threadIdx.x;
    const int wid = tid >> 5, lane = tid & 31;
    const int m0 = blockIdx.y * 128, n0 = blockIdx.x * 128;
    const int wm = wid & 3;
    const int wn = wid >> 2;

    const int ak4 = tid & 15;
    const int am0 = tid >> 4;
    const int kb  = 4 * (wid & 3) + (lane >> 3);
    const int n4b = (lane & 7) + 8 * (wid >> 2);

    float acc[2][8][4];
#pragma unroll
    for (int i = 0; i < 2; i++)
#pragma unroll
        for (int j = 0; j < 8; j++)
#pragma unroll
            for (int q = 0; q < 4; q++) acc[i][j][q] = 0.f;

    const int NC = K / GKC;
    const float* Arow = A + (size_t)m0 * K;

    float4 av[8];
    float4 bv[2][4];

#pragma unroll
    for (int i = 0; i < 8; i++)
        av[i] = *(const float4*)&Arow[(size_t)(am0 + 16 * i) * K + 4 * ak4];
#pragma unroll
    for (int bi = 0; bi < 2; bi++)
#pragma unroll
        for (int r = 0; r < 4; r++)
            bv[bi][r] = *(const float4*)&Bm[(size_t)(4 * kb + r) * N + n0 +
                                            4 * (n4b + 16 * bi)];

    const int a_row = wm * 32 + (lane & 15);
    const int a_kh  = (lane >> 4) << 4;
    const int b_row = wn * 64 + ((lane >> 4) << 3) + (lane & 7);
    const int b_kh  = ((lane >> 3) & 1) << 4;

    for (int c = 0; c < NC; c++) {
        const int buf = c & 1;
        char* st = smem + buf * STG_B;

#pragma unroll
        for (int i = 0; i < 8; i++) {
            int m = am0 + 16 * i;
            uint32_t off = swz(m, 8 * ak4);
            float x0 = av[i].x, x1 = av[i].y, x2 = av[i].z, x3 = av[i].w;
            __nv_bfloat16 h0 = __float2bfloat16(x0), h1 = __float2bfloat16(x1);
            __nv_bfloat16 h2 = __float2bfloat16(x2), h3 = __float2bfloat16(x3);
            uint2 hv, lv;
            hv.x = pk(h0, h1); hv.y = pk(h2, h3);
            lv.x = pk(__float2bfloat16(x0 - __bfloat162float(h0)),
                      __float2bfloat16(x1 - __bfloat162float(h1)));
            lv.y = pk(__float2bfloat16(x2 - __bfloat162float(h2)),
                      __float2bfloat16(x3 - __bfloat162float(h3)));
            *(uint2*)(st + SOFF_AH + off) = hv;
            *(uint2*)(st + SOFF_AL + off) = lv;
        }
#pragma unroll
        for (int bi = 0; bi < 2; bi++) {
            int n4 = n4b + 16 * bi;
            float vr[4][4];
#pragma unroll
            for (int r = 0; r < 4; r++) {
                vr[r][0] = bv[bi][r].x; vr[r][1] = bv[bi][r].y;
                vr[r][2] = bv[bi][r].z; vr[r][3] = bv[bi][r].w;
            }
#pragma unroll
            for (int j = 0; j < 4; j++) {
                uint32_t off = swz(4 * n4 + j, 8 * kb);
                float x0 = vr[0][j], x1 = vr[1][j], x2 = vr[2][j], x3 = vr[3][j];
                __nv_bfloat16 h0 = __float2bfloat16(x0), h1 = __float2bfloat16(x1);
                __nv_bfloat16 h2 = __float2bfloat16(x2), h3 = __float2bfloat16(x3);
                uint2 hv, lv;
                hv.x = pk(h0, h1); hv.y = pk(h2, h3);
                lv.x = pk(__float2bfloat16(x0 - __bfloat162float(h0)),
                          __float2bfloat16(x1 - __bfloat162float(h1)));
                lv.y = pk(__float2bfloat16(x2 - __bfloat162float(h2)),
                          __float2bfloat16(x3 - __bfloat162float(h3)));
                *(uint2*)(st + SOFF_BH + off) = hv;
                *(uint2*)(st + SOFF_BL + off) = lv;
            }
        }
        __syncthreads();

        if (c + 1 < NC) {
            int kc = (c + 1) * GKC;
#pragma unroll
            for (int i = 0; i < 8; i++)
                av[i] = *(const float4*)&Arow[(size_t)(am0 + 16 * i) * K + kc +
                                              4 * ak4];
#pragma unroll
            for (int bi = 0; bi < 2; bi++)
#pragma unroll
                for (int r = 0; r < 4; r++)
                    bv[bi][r] = *(const float4*)&Bm[(size_t)(kc + 4 * kb + r) * N +
                                                    n0 + 4 * (n4b + 16 * bi)];
        }

        const uint32_t sb = sbase + buf * STG_B;
#pragma unroll
        for (int s = 0; s < 4; s++) {
            const uint32_t kbyte = 32 * s;
            uint32_t ah[2][4], al[2][4];
#pragma unroll
            for (int ti = 0; ti < 2; ti++) {
                uint32_t ra = swz(a_row + 16 * ti, kbyte + a_kh);
                ldsm_x4(sb + SOFF_AH + ra, ah[ti][0], ah[ti][1], ah[ti][2], ah[ti][3]);
                ldsm_x4(sb + SOFF_AL + ra, al[ti][0], al[ti][1], al[ti][2], al[ti][3]);
            }
#pragma unroll
            for (int pj = 0; pj < 4; pj++) {
                uint32_t rb = swz(b_row + 16 * pj, kbyte + b_kh);
                uint32_t bh[4], bl[4];
                ldsm_x4(sb + SOFF_BH + rb, bh[0], bh[1], bh[2], bh[3]);
                ldsm_x4(sb + SOFF_BL + rb, bl[0], bl[1], bl[2], bl[3]);
#pragma unroll
                for (int ti = 0; ti < 2; ti++) {
                    mma_bf16(acc[ti][2 * pj + 0], ah[ti], bh + 0);
                    mma_bf16(acc[ti][2 * pj + 1], ah[ti], bh + 2);
                    mma_bf16(acc[ti][2 * pj + 0], ah[ti], bl + 0);
                    mma_bf16(acc[ti][2 * pj + 1], ah[ti], bl + 2);
                    mma_bf16(acc[ti][2 * pj + 0], al[ti], bh + 0);
                    mma_bf16(acc[ti][2 * pj + 1], al[ti], bh + 2);
                }
            }
        }
        __syncthreads();
    }

#pragma unroll
    for (int tj = 0; tj < 8; tj++) {
        int col = n0 + wn * 64 + tj * 8 + 2 * (lane & 3);
        float2 bb = *(const float2*)&bias[col];
#pragma unroll
        for (int ti = 0; ti < 2; ti++) {
            int row = m0 + wm * 32 + ti * 16 + (lane >> 2);
            float2 v0, v1;
            v0.x = acc[ti][tj][0] + bb.x; v0.y = acc[ti][tj][1] + bb.y;
            v1.x = acc[ti][tj][2] + bb.x; v1.y = acc[ti][tj][3] + bb.y;
            *(float2*)&C[(size_t)row * N + col] = v0;
            *(float2*)&C[(size_t)(row + 8) * N + col] = v1;
        }
    }
}

// ---------------------------------------------------------------------------
// RoPE (unchanged)
// ---------------------------------------------------------------------------
__global__ __launch_bounds__(256) void rope_kernel(
    float* __restrict__ qkv,
    const float* __restrict__ cosb, const float* __restrict__ sinb)
{
    int idx = blockIdx.x * blockDim.x + threadIdx.x;
    int d    = idx & 63;
    int head = (idx >> 6) % (NH_ + NKV_);
    int tok  = idx / (64 * (NH_ + NKV_));
    if (tok >= TOK) return;
    int s = tok & (S_ - 1);

    int off = (head < NH_) ? head * HD_ : QSZ + (head - NH_) * HD_;
    float* row = qkv + (size_t)tok * QKVN + off;

    float c  = cosb[s * 64 + d];
    float sn = sinb[s * 64 + d];
    float x1 = row[d];
    float x2 = row[d + 64];
    row[d]      = x1 * c - x2 * sn;
    row[d + 64] = x2 * c + x1 * sn;
}

// ---------------------------------------------------------------------------
// Tensor-core flash attention (mma.sync bf16, hi/lo emulated fp32).
// Block: 128 q-rows x (head, batch). 8 warps x m16. K-tiles of 64 keys.
// QK^T: Qh*Kh + Qh*Kl + Ql*Kh.  PV: Ph*Vh + Pl*Vh + Ph*Vl (P from regs).
// SMEM: Q hi/lo 64KB + K hi/lo 32KB + V^T hi/lo 32KB = 128KB, 1 buffer,
// K/V of next tile prefetched into registers during compute.
// ---------------------------------------------------------------------------
#define AQT 128
#define AKT 64
#define AQH 0
#define AQL 32768
#define AKH 65536
#define AKL 81920
#define AVH 98304
#define AVL 114688
#define ATTN2_SMEM 131072

__global__ __launch_bounds__(256, 1) void attn_mma_kernel(
    const float* __restrict__ qkv, float* __restrict__ out)
{
    extern __shared__ char sm[];
    const uint32_t sb = smem_u32(sm);
    const int tid = threadIdx.x;
    const int wid = tid >> 5, lane = tid & 31;
    const int q0 = blockIdx.x * AQT;
    const int h  = blockIdx.y;
    const int b  = blockIdx.z;
    const int kvh = h >> 2;

    const float scale = 0.08838834764831845f;   // 1/sqrt(128)
    const size_t tok0 = (size_t)b * S_;
    const float* qbase = qkv + (tok0 + q0) * QKVN + h * HD_;
    const float* kbase = qkv + tok0 * QKVN + QSZ + kvh * HD_;
    const float* vbase = qkv + tok0 * QKVN + QSZ + KVSZ + kvh * HD_;

    // producer constants
    const int hd4 = tid & 31;        // float4 index over 128 hd
    const int pr0 = tid >> 5;        // row base (stride 8)
    const int vkb  = 4 * (wid & 3) + (lane >> 3);   // V: key block 0..15
    const int vn4b = (lane & 7) + 8 * (wid >> 2);   // V: hd float4 base 0..15

    // ---- Q: load + split + STS (256B swizzled rows) ----
#pragma unroll 4
    for (int i = 0; i < 16; i++) {
        int r = pr0 + 8 * i;
        float4 v = *(const float4*)&qbase[(size_t)r * QKVN + 4 * hd4];
        uint32_t off = swz256(r, 8 * hd4);
        float x0 = v.x, x1 = v.y, x2 = v.z, x3 = v.w;
        __nv_bfloat16 h0 = __float2bfloat16(x0), h1 = __float2bfloat16(x1);
        __nv_bfloat16 h2 = __float2bfloat16(x2), h3 = __float2bfloat16(x3);
        uint2 hv, lv;
        hv.x = pk(h0, h1); hv.y = pk(h2, h3);
        lv.x = pk(__float2bfloat16(x0 - __bfloat162float(h0)),
                  __float2bfloat16(x1 - __bfloat162float(h1)));
        lv.y = pk(__float2bfloat16(x2 - __bfloat162float(h2)),
                  __float2bfloat16(x3 - __bfloat162float(h3)));
        *(uint2*)(sm + AQH + off) = hv;
        *(uint2*)(sm + AQL + off) = lv;
    }

    // ---- prefetch K/V tile 0 into registers ----
    float4 kv4[8];
    float4 vv4[2][4];
#pragma unroll
    for (int i = 0; i < 8; i++)
        kv4[i] = *(const float4*)&kbase[(size_t)(pr0 + 8 * i) * QKVN + 4 * hd4];
#pragma unroll
    for (int bi = 0; bi < 2; bi++)
#pragma unroll
        for (int r = 0; r < 4; r++)
            vv4[bi][r] = *(const float4*)&vbase[(size_t)(4 * vkb + r) * QKVN +
                                                4 * (vn4b + 16 * bi)];

    // accumulators
    float o[16][4];
#pragma unroll
    for (int j = 0; j < 16; j++)
#pragma unroll
        for (int q = 0; q < 4; q++) o[j][q] = 0.f;
    float m0r = -1e30f, m1r = -1e30f, l0r = 0.f, l1r = 0.f;

    // consumer ldmatrix address constants
    const int a_row = wid * 16 + (lane & 15);
    const int a_kh  = (lane >> 4) << 4;
    const int b_rsub = ((lane >> 4) << 3) + (lane & 7);
    const int b_kh   = ((lane >> 3) & 1) << 4;

    const int NT = S_ / AKT;   // 32
    for (int t = 0; t < NT; t++) {
        // ---- STS K (keys rows, 256B) ----
#pragma unroll
        for (int i = 0; i < 8; i++) {
            int r = pr0 + 8 * i;
            uint32_t off = swz256(r, 8 * hd4);
            float x0 = kv4[i].x, x1 = kv4[i].y, x2 = kv4[i].z, x3 = kv4[i].w;
            __nv_bfloat16 h0 = __float2bfloat16(x0), h1 = __float2bfloat16(x1);
            __nv_bfloat16 h2 = __float2bfloat16(x2), h3 = __float2bfloat16(x3);
            uint2 hv, lv;
            hv.x = pk(h0, h1); hv.y = pk(h2, h3);
            lv.x = pk(__float2bfloat16(x0 - __bfloat162float(h0)),
                      __float2bfloat16(x1 - __bfloat162float(h1)));
            lv.y = pk(__float2bfloat16(x2 - __bfloat162float(h2)),
                      __float2bfloat16(x3 - __bfloat162float(h3)));
            *(uint2*)(sm + AKH + off) = hv;
            *(uint2*)(sm + AKL + off) = lv;
        }
        // ---- STS V transposed -> [hd][keys], 128B rows ----
#pragma unroll
        for (int bi = 0; bi < 2; bi++) {
            int n4 = vn4b + 16 * bi;
            float vr[4][4];
#pragma unroll
            for (int r = 0; r < 4; r++) {
                vr[r][0] = vv4[bi][r].x; vr[r][1] = vv4[bi][r].y;
                vr[r][2] = vv4[bi][r].z; vr[r][3] = vv4[bi][r].w;
            }
#pragma unroll
            for (int j = 0; j < 4; j++) {
                uint32_t off = swz(4 * n4 + j, 8 * vkb);
                float x0 = vr[0][j], x1 = vr[1][j], x2 = vr[2][j], x3 = vr[3][j];
                __nv_bfloat16 h0 = __float2bfloat16(x0), h1 = __float2bfloat16(x1);
                __nv_bfloat16 h2 = __float2bfloat16(x2), h3 = __float2bfloat16(x3);
                uint2 hv, lv;
                hv.x = pk(h0, h1); hv.y = pk(h2, h3);
                lv.x = pk(__float2bfloat16(x0 - __bfloat162float(h0)),
                          __float2bfloat16(x1 - __bfloat162float(h1)));
                lv.y = pk(__float2bfloat16(x2 - __bfloat162float(h2)),
                          __float2bfloat16(x3 - __bfloat162float(h3)));
                *(uint2*)(sm + AVH + off) = hv;
                *(uint2*)(sm + AVL + off) = lv;
            }
        }
        __syncthreads();

        // ---- prefetch tile t+1 ----
        if (t + 1 < NT) {
            const float* kp = kbase + (size_t)(t + 1) * AKT * QKVN;
            const float* vp = vbase + (size_t)(t + 1) * AKT * QKVN;
#pragma unroll
            for (int i = 0; i < 8; i++)
                kv4[i] = *(const float4*)&kp[(size_t)(pr0 + 8 * i) * QKVN + 4 * hd4];
#pragma unroll
            for (int bi = 0; bi < 2; bi++)
#pragma unroll
                for (int r = 0; r < 4; r++)
                    vv4[bi][r] = *(const float4*)&vp[(size_t)(4 * vkb + r) * QKVN +
                                                    4 * (vn4b + 16 * bi)];
        }

        // ---- QK^T: sc[8][4] over 64 keys ----
        float sc[8][4];
#pragma unroll
        for (int j = 0; j < 8; j++)
#pragma unroll
            for (int q = 0; q < 4; q++) sc[j][q] = 0.f;

#pragma unroll
        for (int s = 0; s < 8; s++) {
            uint32_t ra = swz256(a_row, s * 32 + a_kh);
            uint32_t ah[4], al[4];
            ldsm_x4(sb + AQH + ra, ah[0], ah[1], ah[2], ah[3]);
            ldsm_x4(sb + AQL + ra, al[0], al[1], al[2], al[3]);
#pragma unroll
            for (int nb = 0; nb < 4; nb++) {
                uint32_t rb = swz256(nb * 16 + b_rsub, s * 32 + b_kh);
                uint32_t bh[4], bl[4];
                ldsm_x4(sb + AKH + rb, bh[0], bh[1], bh[2], bh[3]);
                ldsm_x4(sb + AKL + rb, bl[0], bl[1], bl[2], bl[3]);
                mma_bf16(sc[2 * nb + 0], ah, bh + 0);
                mma_bf16(sc[2 * nb + 1], ah, bh + 2);
                mma_bf16(sc[2 * nb + 0], ah, bl + 0);
                mma_bf16(sc[2 * nb + 1], ah, bl + 2);
                mma_bf16(sc[2 * nb + 0], al, bh + 0);
                mma_bf16(sc[2 * nb + 1], al, bh + 2);
            }
        }

        // ---- online softmax (rows r0=lane>>2, r1=r0+8) ----
        float mx0 = -1e30f, mx1 = -1e30f;
#pragma unroll
        for (int j = 0; j < 8; j++) {
            sc[j][0] *= scale; sc[j][1] *= scale;
            sc[j][2] *= scale; sc[j][3] *= scale;
            mx0 = fmaxf(mx0, fmaxf(sc[j][0], sc[j][1]));
            mx1 = fmaxf(mx1, fmaxf(sc[j][2], sc[j][3]));
        }
        mx0 = fmaxf(mx0, __shfl_xor_sync(0xffffffffu, mx0, 1));
        mx0 = fmaxf(mx0, __shfl_xor_sync(0xffffffffu, mx0, 2));
        mx1 = fmaxf(mx1, __shfl_xor_sync(0xffffffffu, mx1, 1));
        mx1 = fmaxf(mx1, __shfl_xor_sync(0xffffffffu, mx1, 2));
        float mn0 = fmaxf(m0r, mx0), mn1 = fmaxf(m1r, mx1);
        float al0 = __expf(m0r - mn0), al1 = __expf(m1r - mn1);

        float ls0 = 0.f, ls1 = 0.f;
        uint32_t pa[4][4], pal[4][4];
#pragma unroll
        for (int j = 0; j < 8; j++) {
            float p00 = __expf(sc[j][0] - mn0);
            float p01 = __expf(sc[j][1] - mn0);
            float p10 = __expf(sc[j][2] - mn1);
            float p11 = __expf(sc[j][3] - mn1);
            ls0 += p00 + p01; ls1 += p10 + p11;
            __nv_bfloat16 h00 = __float2bfloat16(p00), h01 = __float2bfloat16(p01);
            __nv_bfloat16 h10 = __float2bfloat16(p10), h11 = __float2bfloat16(p11);
            int kk = j >> 1, hf = (j & 1) << 1;
            pa[kk][hf + 0] = pk(h00, h01);
            pa[kk][hf + 1] = pk(h10, h11);
            pal[kk][hf + 0] = pk(__float2bfloat16(p00 - __bfloat162float(h00)),
                                 __float2bfloat16(p01 - __bfloat162float(h01)));
            pal[kk][hf + 1] = pk(__float2bfloat16(p10 - __bfloat162float(h10)),
                                 __float2bfloat16(p11 - __bfloat162float(h11)));
        }
        ls0 += __shfl_xor_sync(0xffffffffu, ls0, 1);
        ls0 += __shfl_xor_sync(0xffffffffu, ls0, 2);
        ls1 += __shfl_xor_sync(0xffffffffu, ls1, 1);
        ls1 += __shfl_xor_sync(0xffffffffu, ls1, 2);
        l0r = l0r * al0 + ls0;
        l1r = l1r * al1 + ls1;
        m0r = mn0; m1r = mn1;
#pragma unroll
        for (int j = 0; j < 16; j++) {
            o[j][0] *= al0; o[j][1] *= al0;
            o[j][2] *= al1; o[j][3] *= al1;
        }

        // ---- PV: o += P(128x64) @ V(64x128) ----
#pragma unroll
        for (int kk = 0; kk < 4; kk++) {
#pragma unroll
            for (int nb = 0; nb < 8; nb++) {
                uint32_t rv = swz(nb * 16 + b_rsub, kk * 32 + b_kh);
                uint32_t vh[4], vl[4];
                ldsm_x4(sb + AVH + rv, vh[0], vh[1], vh[2], vh[3]);
                ldsm_x4(sb + AVL + rv, vl[0], vl[1], vl[2], vl[3]);
                mma_bf16(o[2 * nb + 0], pa[kk], vh + 0);
                mma_bf16(o[2 * nb + 1], pa[kk], vh + 2);
                mma_bf16(o[2 * nb + 0], pal[kk], vh + 0);
                mma_bf16(o[2 * nb + 1], pal[kk], vh + 2);
                mma_bf16(o[2 * nb + 0], pa[kk], vl + 0);
                mma_bf16(o[2 * nb + 1], pa[kk], vl + 2);
            }
        }
        __syncthreads();
    }

    // ---- epilogue ----
    float inv0 = 1.f / l0r, inv1 = 1.f / l1r;
    int r0 = lane >> 2, c2 = 2 * (lane & 3);
    size_t row0 = (size_t)b * S_ + q0 + wid * 16 + r0;
#pragma unroll
    for (int j = 0; j < 16; j++) {
        int col = h * HD_ + 8 * j + c2;
        float2 v0, v1;
        v0.x = o[j][0] * inv0; v0.y = o[j][1] * inv0;
        v1.x = o[j][2] * inv1; v1.y = o[j][3] * inv1;
        *(float2*)&out[row0 * HID_ + col] = v0;
        *(float2*)&out[(row0 + 8) * HID_ + col] = v1;
    }
}

// ---------------------------------------------------------------------------
// kernel_launch
// ---------------------------------------------------------------------------
extern "C" void kernel_launch(void* const* d_in, const int* in_sizes, int n_in,
                              void* d_out, int out_size)
{
    const float *hidden = nullptr, *cosb = nullptr, *sinb = nullptr;
    const float *wqkv = nullptr, *bqkv = nullptr, *wo = nullptr, *bo = nullptr;
    for (int i = 0; i < n_in; i++) {
        long sz = in_sizes[i];
        const float* p = (const float*)d_in[i];
        if (sz == (long)TOK * HID_)            hidden = p;
        else if (sz == (long)S_ * 64) {
            if (!cosb) cosb = p; else sinb = p;
        }
        else if (sz == (long)HID_ * QKVN)      wqkv = p;
        else if (sz == (long)QKVN)             bqkv = p;
        else if (sz == (long)HID_ * HID_)      wo = p;
        else if (sz == (long)HID_)             bo = p;
    }
    float* out = (float*)d_out;

    float *qkv = nullptr, *attn = nullptr;
    cudaGetSymbolAddress((void**)&qkv, g_qkv);
    cudaGetSymbolAddress((void**)&attn, g_attn);

    cudaFuncSetAttribute(gemm3x_kernel,
                         cudaFuncAttributeMaxDynamicSharedMemorySize, GEMM_SMEM);
    cudaFuncSetAttribute(attn_mma_kernel,
                         cudaFuncAttributeMaxDynamicSharedMemorySize, ATTN2_SMEM);

    // 1) QKV projection
    {
        dim3 grid(QKVN / 128, TOK / 128);  // (24, 64)
        gemm3x_kernel<<<grid, 256, GEMM_SMEM>>>(hidden, wqkv, bqkv, qkv,
                                                TOK, QKVN, HID_);
    }
    // 2) RoPE
    {
        int total = TOK * (NH_ + NKV_) * 64;
        rope_kernel<<<total / 256, 256>>>(qkv, cosb, sinb);
    }
    // 3) Attention (tensor-core)
    {
        dim3 grid(S_ / AQT, NH_, B_);  // (16, 16, 4)
        attn_mma_kernel<<<grid, 256, ATTN2_SMEM>>>(qkv, attn);
    }
    // 4) Output projection
    {
        dim3 grid(HID_ / 128, TOK / 128);  // (16, 64)
        gemm3x_kernel<<<grid, 256, GEMM_SMEM>>>(attn, wo, bo, out,
                                                TOK, HID_, HID_);
    }
}

// round 6
// speedup vs baseline: 3.2292x; 1.0419x over previous
#include <cuda_runtime.h>
#include <cuda_bf16.h>
#include <cstdint>
#include <math.h>

// ---------------------------------------------------------------------------
// Problem constants: B=4, S=2048, HID=2048, NH=16, NKV=4, HD=128.
// ---------------------------------------------------------------------------
#define B_    4
#define S_    2048
#define HID_  2048
#define NH_   16
#define NKV_  4
#define HD_   128
#define QSZ   (NH_ * HD_)          // 2048
#define KVSZ  (NKV_ * HD_)         // 512
#define QKVN  (QSZ + 2 * KVSZ)     // 3072
#define TOK   (B_ * S_)            // 8192

// Scratch (device globals; no allocs allowed)
__device__ __align__(16) float          g_qkv[(size_t)TOK * QKVN];
__device__ __align__(16) float          g_attn[(size_t)TOK * HID_];
__device__ __align__(16) __nv_bfloat16  g_wqkv_h[(size_t)QKVN * HID_];  // [N][K]
__device__ __align__(16) __nv_bfloat16  g_wqkv_l[(size_t)QKVN * HID_];
__device__ __align__(16) __nv_bfloat16  g_wo_h[(size_t)HID_ * HID_];    // [N][K]
__device__ __align__(16) __nv_bfloat16  g_wo_l[(size_t)HID_ * HID_];
__device__ __align__(16) __nv_bfloat16  g_qkvb_h[(size_t)TOK * QKVN];   // rope'd q,k
__device__ __align__(16) __nv_bfloat16  g_qkvb_l[(size_t)TOK * QKVN];

// ---------------------------------------------------------------------------
// Helpers
// ---------------------------------------------------------------------------
__device__ __forceinline__ uint32_t smem_u32(const void* p) {
    uint32_t a;
    asm("{ .reg .u64 t; cvta.to.shared.u64 t, %1; cvt.u32.u64 %0, t; }"
        : "=r"(a) : "l"(p));
    return a;
}
__device__ __forceinline__ void ldsm_x4(uint32_t addr, uint32_t& r0, uint32_t& r1,
                                        uint32_t& r2, uint32_t& r3) {
    asm volatile("ldmatrix.sync.aligned.m8n8.x4.shared.b16 {%0,%1,%2,%3}, [%4];"
                 : "=r"(r0), "=r"(r1), "=r"(r2), "=r"(r3) : "r"(addr));
}
__device__ __forceinline__ void mma_bf16(float* d, const uint32_t* a,
                                         const uint32_t* b) {
    asm volatile(
        "mma.sync.aligned.m16n8k16.row.col.f32.bf16.bf16.f32 "
        "{%0,%1,%2,%3}, {%4,%5,%6,%7}, {%8,%9}, {%0,%1,%2,%3};"
        : "+f"(d[0]), "+f"(d[1]), "+f"(d[2]), "+f"(d[3])
        : "r"(a[0]), "r"(a[1]), "r"(a[2]), "r"(a[3]), "r"(b[0]), "r"(b[1]));
}
__device__ __forceinline__ uint32_t pk(__nv_bfloat16 a, __nv_bfloat16 b) {
    __nv_bfloat162 t = __halves2bfloat162(a, b);
    return *reinterpret_cast<uint32_t*>(&t);
}
__device__ __forceinline__ void split1(float x, __nv_bfloat16& h, __nv_bfloat16& l) {
    h = __float2bfloat16(x);
    l = __float2bfloat16(x - __bfloat162float(h));
}
// swizzled byte offset, 128-byte rows (64 bf16)
__device__ __forceinline__ uint32_t swz(uint32_t row, uint32_t kbyte) {
    return (row * 128 + kbyte) ^ ((row & 7) << 4);
}
// swizzled byte offset, 256-byte rows (128 bf16)
__device__ __forceinline__ uint32_t swz256(uint32_t row, uint32_t kbyte) {
    return (row * 256 + kbyte) ^ ((row & 7) << 4);
}

// ---------------------------------------------------------------------------
// W [K][N] fp32 -> WhT/WlT [N][K] bf16 (tiled transpose + split)
// ---------------------------------------------------------------------------
__global__ __launch_bounds__(256) void split_wT_kernel(
    const float* __restrict__ W, __nv_bfloat16* __restrict__ WhT,
    __nv_bfloat16* __restrict__ WlT, int K, int N)
{
    __shared__ float tile[32][33];
    int nb = blockIdx.x * 32, kb = blockIdx.y * 32;
    int tx = threadIdx.x & 31, ty = threadIdx.x >> 5;   // 32 x 8
#pragma unroll
    for (int r = 0; r < 4; r++)
        tile[ty + 8 * r][tx] = W[(size_t)(kb + ty + 8 * r) * N + nb + tx];
    __syncthreads();
#pragma unroll
    for (int r = 0; r < 4; r++) {
        int n = nb + ty + 8 * r, k = kb + tx;
        float x = tile[tx][ty + 8 * r];
        __nv_bfloat16 h, l;
        split1(x, h, l);
        WhT[(size_t)n * K + k] = h;
        WlT[(size_t)n * K + k] = l;
    }
}

// ---------------------------------------------------------------------------
// qkv fp32 -> rope'd bf16 hi/lo (q + k heads only; v read as fp32 elsewhere)
// ---------------------------------------------------------------------------
__global__ __launch_bounds__(256) void rope_split_kernel(
    const float* __restrict__ qkv,
    const float* __restrict__ cosb, const float* __restrict__ sinb,
    __nv_bfloat16* __restrict__ oh, __nv_bfloat16* __restrict__ ol)
{
    int idx = blockIdx.x * blockDim.x + threadIdx.x;   // TOK * 1280
    int p   = idx % 1280;
    int tok = idx / 1280;
    if (tok >= TOK) return;
    int s = tok & (S_ - 1);
    size_t base = (size_t)tok * QKVN;

    int head = p >> 6, d = p & 63;
    int off = (head < NH_) ? head * HD_ : QSZ + (head - NH_) * HD_;
    float c  = cosb[s * 64 + d];
    float sn = sinb[s * 64 + d];
    float x1 = qkv[base + off + d];
    float x2 = qkv[base + off + d + 64];
    float y1 = x1 * c - x2 * sn;
    float y2 = x2 * c + x1 * sn;
    __nv_bfloat16 h, l;
    split1(y1, h, l);
    oh[base + off + d] = h; ol[base + off + d] = l;
    split1(y2, h, l);
    oh[base + off + d + 64] = h; ol[base + off + d + 64] = l;
}

// ---------------------------------------------------------------------------
// bf16x3 mma.sync GEMM (R4 structure). A fp32 [M][K] (split in-kernel);
// B pre-split bf16 [N][K] (direct STS). Tile 128x128, K-chunk 64, 2 buffers.
// ---------------------------------------------------------------------------
#define GKC     64
#define STG_B   65536
#define SOFF_AH 0
#define SOFF_AL 16384
#define SOFF_BH 32768
#define SOFF_BL 49152
#define GEMM_SMEM (2 * STG_B)

__global__ __launch_bounds__(256, 1) void gemm3x_kernel(
    const float* __restrict__ A,
    const __nv_bfloat16* __restrict__ BhT, const __nv_bfloat16* __restrict__ BlT,
    const float* __restrict__ bias, float* __restrict__ C,
    int M, int N, int K)
{
    extern __shared__ char smem[];
    const uint32_t sbase = smem_u32(smem);
    const int tid = threadIdx.x;
    const int wid = tid >> 5, lane = tid & 31;
    const int m0 = blockIdx.y * 128, n0 = blockIdx.x * 128;
    const int wm = wid & 3;
    const int wn = wid >> 2;

    const int ak4 = tid & 15;   // A: k-float4 (k = 4*ak4)
    const int am0 = tid >> 4;   // A: m base (m = am0 + 16*i)

    float acc[2][8][4];
#pragma unroll
    for (int i = 0; i < 2; i++)
#pragma unroll
        for (int j = 0; j < 8; j++)
#pragma unroll
            for (int q = 0; q < 4; q++) acc[i][j][q] = 0.f;

    const int NC = K / GKC;
    const float* Arow = A + (size_t)m0 * K;

    float4 av[8];
    uint4  bh4[4], bl4[4];

    // ---- prologue: LDG chunk 0 ----
#pragma unroll
    for (int i = 0; i < 8; i++)
        av[i] = *(const float4*)&Arow[(size_t)(am0 + 16 * i) * K + 4 * ak4];
#pragma unroll
    for (int i = 0; i < 4; i++) {
        int u = tid + 256 * i;
        int row = u >> 3, ks = u & 7;
        bh4[i] = *(const uint4*)&BhT[(size_t)(n0 + row) * K + ks * 8];
        bl4[i] = *(const uint4*)&BlT[(size_t)(n0 + row) * K + ks * 8];
    }

    const int a_row = wm * 32 + (lane & 15);
    const int a_kh  = (lane >> 4) << 4;
    const int b_row = wn * 64 + ((lane >> 4) << 3) + (lane & 7);
    const int b_kh  = ((lane >> 3) & 1) << 4;

    for (int c = 0; c < NC; c++) {
        const int buf = c & 1;
        char* st = smem + buf * STG_B;

        // ---- A split + store (identical to R4) ----
#pragma unroll
        for (int i = 0; i < 8; i++) {
            int m = am0 + 16 * i;
            uint32_t off = swz(m, 8 * ak4);
            float x0 = av[i].x, x1 = av[i].y, x2 = av[i].z, x3 = av[i].w;
            __nv_bfloat16 h0, l0, h1, l1, h2, l2, h3, l3;
            split1(x0, h0, l0); split1(x1, h1, l1);
            split1(x2, h2, l2); split1(x3, h3, l3);
            uint2 hv, lv;
            hv.x = pk(h0, h1); hv.y = pk(h2, h3);
            lv.x = pk(l0, l1); lv.y = pk(l2, l3);
            *(uint2*)(st + SOFF_AH + off) = hv;
            *(uint2*)(st + SOFF_AL + off) = lv;
        }
        // ---- B direct store (pre-split; same SMEM layout as R4) ----
#pragma unroll
        for (int i = 0; i < 4; i++) {
            int u = tid + 256 * i;
            int row = u >> 3, ks = u & 7;
            uint32_t off = swz(row, ks * 16);
            *(uint4*)(st + SOFF_BH + off) = bh4[i];
            *(uint4*)(st + SOFF_BL + off) = bl4[i];
        }
        __syncthreads();

        // ---- LDG chunk c+1 ----
        if (c + 1 < NC) {
            int kc = (c + 1) * GKC;
#pragma unroll
            for (int i = 0; i < 8; i++)
                av[i] = *(const float4*)&Arow[(size_t)(am0 + 16 * i) * K + kc +
                                              4 * ak4];
#pragma unroll
            for (int i = 0; i < 4; i++) {
                int u = tid + 256 * i;
                int row = u >> 3, ks = u & 7;
                bh4[i] = *(const uint4*)&BhT[(size_t)(n0 + row) * K + kc + ks * 8];
                bl4[i] = *(const uint4*)&BlT[(size_t)(n0 + row) * K + kc + ks * 8];
            }
        }

        // ---- compute (identical to R4) ----
        const uint32_t sb = sbase + buf * STG_B;
#pragma unroll
        for (int s = 0; s < 4; s++) {
            const uint32_t kbyte = 32 * s;
            uint32_t ah[2][4], al[2][4];
#pragma unroll
            for (int ti = 0; ti < 2; ti++) {
                uint32_t ra = swz(a_row + 16 * ti, kbyte + a_kh);
                ldsm_x4(sb + SOFF_AH + ra, ah[ti][0], ah[ti][1], ah[ti][2], ah[ti][3]);
                ldsm_x4(sb + SOFF_AL + ra, al[ti][0], al[ti][1], al[ti][2], al[ti][3]);
            }
#pragma unroll
            for (int pj = 0; pj < 4; pj++) {
                uint32_t rb = swz(b_row + 16 * pj, kbyte + b_kh);
                uint32_t bh[4], bl[4];
                ldsm_x4(sb + SOFF_BH + rb, bh[0], bh[1], bh[2], bh[3]);
                ldsm_x4(sb + SOFF_BL + rb, bl[0], bl[1], bl[2], bl[3]);
#pragma unroll
                for (int ti = 0; ti < 2; ti++) {
                    mma_bf16(acc[ti][2 * pj + 0], ah[ti], bh + 0);
                    mma_bf16(acc[ti][2 * pj + 1], ah[ti], bh + 2);
                    mma_bf16(acc[ti][2 * pj + 0], ah[ti], bl + 0);
                    mma_bf16(acc[ti][2 * pj + 1], ah[ti], bl + 2);
                    mma_bf16(acc[ti][2 * pj + 0], al[ti], bh + 0);
                    mma_bf16(acc[ti][2 * pj + 1], al[ti], bh + 2);
                }
            }
        }
        __syncthreads();
    }

    // ---- epilogue (R4) ----
#pragma unroll
    for (int tj = 0; tj < 8; tj++) {
        int col = n0 + wn * 64 + tj * 8 + 2 * (lane & 3);
        float2 bb = *(const float2*)&bias[col];
#pragma unroll
        for (int ti = 0; ti < 2; ti++) {
            int row = m0 + wm * 32 + ti * 16 + (lane >> 2);
            float2 v0, v1;
            v0.x = acc[ti][tj][0] + bb.x; v0.y = acc[ti][tj][1] + bb.y;
            v1.x = acc[ti][tj][2] + bb.x; v1.y = acc[ti][tj][3] + bb.y;
            *(float2*)&C[(size_t)row * N + col] = v0;
            *(float2*)&C[(size_t)(row + 8) * N + col] = v1;
        }
    }
}

// ---------------------------------------------------------------------------
// Tensor-core flash attention (R4 structure & consumer, producers lightened:
// Q/K direct-STS from pre-split rope'd bf16; V from fp32 qkv as in R4).
// ---------------------------------------------------------------------------
#define AQH 0
#define AQL 32768
#define AKH 65536
#define AKL 81920
#define AVH 98304
#define AVL 114688
#define ATTN2_SMEM 131072

__global__ __launch_bounds__(256, 1) void attn_mma_kernel(
    const __nv_bfloat16* __restrict__ qh, const __nv_bfloat16* __restrict__ ql,
    const float* __restrict__ qkv, float* __restrict__ out)
{
    extern __shared__ char sm[];
    const uint32_t sb = smem_u32(sm);
    const int tid = threadIdx.x;
    const int wid = tid >> 5, lane = tid & 31;
    const int q0 = blockIdx.x * 128;
    const int h  = blockIdx.y;
    const int b  = blockIdx.z;
    const int kvh = h >> 2;

    const float scale = 0.08838834764831845f;   // 1/sqrt(128)
    const size_t tok0 = (size_t)b * S_;
    const __nv_bfloat16* qbh = qh + (tok0 + q0) * QKVN + h * HD_;
    const __nv_bfloat16* qbl = ql + (tok0 + q0) * QKVN + h * HD_;
    const __nv_bfloat16* kbh = qh + tok0 * QKVN + QSZ + kvh * HD_;
    const __nv_bfloat16* kbl = ql + tok0 * QKVN + QSZ + kvh * HD_;
    const float* vbase = qkv + tok0 * QKVN + QSZ + KVSZ + kvh * HD_;

    // V producer constants (R4)
    const int vkb  = 4 * (wid & 3) + (lane >> 3);   // V: key block 0..15
    const int vn4b = (lane & 7) + 8 * (wid >> 2);   // V: hd float4 base 0..15

    // ---- Q: direct STS from pre-split bf16 (same layout as R4) ----
#pragma unroll
    for (int i = 0; i < 8; i++) {
        int u = tid + 256 * i;
        int row = u >> 4, ks = u & 15;
        uint32_t off = swz256(row, ks * 16);
        *(uint4*)(sm + AQH + off) = *(const uint4*)&qbh[(size_t)row * QKVN + ks * 8];
        *(uint4*)(sm + AQL + off) = *(const uint4*)&qbl[(size_t)row * QKVN + ks * 8];
    }

    // ---- prefetch K/V tile 0 into registers ----
    uint4  kh4[4], kl4[4];
    float4 vv4[2][4];
#pragma unroll
    for (int i = 0; i < 4; i++) {
        int u = tid + 256 * i;
        int row = u >> 4, ks = u & 15;
        kh4[i] = *(const uint4*)&kbh[(size_t)row * QKVN + ks * 8];
        kl4[i] = *(const uint4*)&kbl[(size_t)row * QKVN + ks * 8];
    }
#pragma unroll
    for (int bi = 0; bi < 2; bi++)
#pragma unroll
        for (int r = 0; r < 4; r++)
            vv4[bi][r] = *(const float4*)&vbase[(size_t)(4 * vkb + r) * QKVN +
                                                4 * (vn4b + 16 * bi)];

    // accumulators
    float o[16][4];
#pragma unroll
    for (int j = 0; j < 16; j++)
#pragma unroll
        for (int q = 0; q < 4; q++) o[j][q] = 0.f;
    float m0r = -1e30f, m1r = -1e30f, l0r = 0.f, l1r = 0.f;

    // consumer ldmatrix address constants (R4)
    const int a_row = wid * 16 + (lane & 15);
    const int a_kh  = (lane >> 4) << 4;
    const int b_rsub = ((lane >> 4) << 3) + (lane & 7);
    const int b_kh   = ((lane >> 3) & 1) << 4;

    const int NT = S_ / 64;   // 32
    for (int t = 0; t < NT; t++) {
        __syncthreads();  // previous tile's consumers done (covers Q STS too)

        // ---- STS K (direct, 256B swizzled rows — same layout as R4) ----
#pragma unroll
        for (int i = 0; i < 4; i++) {
            int u = tid + 256 * i;
            int row = u >> 4, ks = u & 15;
            uint32_t off = swz256(row, ks * 16);
            *(uint4*)(sm + AKH + off) = kh4[i];
            *(uint4*)(sm + AKL + off) = kl4[i];
        }
        // ---- STS V transposed -> [hd][keys] (R4 exact) ----
#pragma unroll
        for (int bi = 0; bi < 2; bi++) {
            int n4 = vn4b + 16 * bi;
            float vr[4][4];
#pragma unroll
            for (int r = 0; r < 4; r++) {
                vr[r][0] = vv4[bi][r].x; vr[r][1] = vv4[bi][r].y;
                vr[r][2] = vv4[bi][r].z; vr[r][3] = vv4[bi][r].w;
            }
#pragma unroll
            for (int j = 0; j < 4; j++) {
                uint32_t off = swz(4 * n4 + j, 8 * vkb);
                float x0 = vr[0][j], x1 = vr[1][j], x2 = vr[2][j], x3 = vr[3][j];
                __nv_bfloat16 h0, l0, h1, l1, h2, l2, h3, l3;
                split1(x0, h0, l0); split1(x1, h1, l1);
                split1(x2, h2, l2); split1(x3, h3, l3);
                uint2 hv, lv;
                hv.x = pk(h0, h1); hv.y = pk(h2, h3);
                lv.x = pk(l0, l1); lv.y = pk(l2, l3);
                *(uint2*)(sm + AVH + off) = hv;
                *(uint2*)(sm + AVL + off) = lv;
            }
        }
        __syncthreads();

        // ---- prefetch tile t+1 ----
        if (t + 1 < NT) {
            size_t tb = (size_t)(t + 1) * 64;
#pragma unroll
            for (int i = 0; i < 4; i++) {
                int u = tid + 256 * i;
                int row = u >> 4, ks = u & 15;
                kh4[i] = *(const uint4*)&kbh[(tb + row) * QKVN + ks * 8];
                kl4[i] = *(const uint4*)&kbl[(tb + row) * QKVN + ks * 8];
            }
            const float* vp = vbase + tb * QKVN;
#pragma unroll
            for (int bi = 0; bi < 2; bi++)
#pragma unroll
                for (int r = 0; r < 4; r++)
                    vv4[bi][r] = *(const float4*)&vp[(size_t)(4 * vkb + r) * QKVN +
                                                    4 * (vn4b + 16 * bi)];
        }

        // ---- QK^T (R4 exact) ----
        float sc[8][4];
#pragma unroll
        for (int j = 0; j < 8; j++)
#pragma unroll
            for (int q = 0; q < 4; q++) sc[j][q] = 0.f;

#pragma unroll
        for (int s = 0; s < 8; s++) {
            uint32_t ra = swz256(a_row, s * 32 + a_kh);
            uint32_t ah[4], al[4];
            ldsm_x4(sb + AQH + ra, ah[0], ah[1], ah[2], ah[3]);
            ldsm_x4(sb + AQL + ra, al[0], al[1], al[2], al[3]);
#pragma unroll
            for (int nb = 0; nb < 4; nb++) {
                uint32_t rb = swz256(nb * 16 + b_rsub, s * 32 + b_kh);
                uint32_t bh[4], bl[4];
                ldsm_x4(sb + AKH + rb, bh[0], bh[1], bh[2], bh[3]);
                ldsm_x4(sb + AKL + rb, bl[0], bl[1], bl[2], bl[3]);
                mma_bf16(sc[2 * nb + 0], ah, bh + 0);
                mma_bf16(sc[2 * nb + 1], ah, bh + 2);
                mma_bf16(sc[2 * nb + 0], ah, bl + 0);
                mma_bf16(sc[2 * nb + 1], ah, bl + 2);
                mma_bf16(sc[2 * nb + 0], al, bh + 0);
                mma_bf16(sc[2 * nb + 1], al, bh + 2);
            }
        }

        // ---- online softmax (R4 exact) ----
        float mx0 = -1e30f, mx1 = -1e30f;
#pragma unroll
        for (int j = 0; j < 8; j++) {
            sc[j][0] *= scale; sc[j][1] *= scale;
            sc[j][2] *= scale; sc[j][3] *= scale;
            mx0 = fmaxf(mx0, fmaxf(sc[j][0], sc[j][1]));
            mx1 = fmaxf(mx1, fmaxf(sc[j][2], sc[j][3]));
        }
        mx0 = fmaxf(mx0, __shfl_xor_sync(0xffffffffu, mx0, 1));
        mx0 = fmaxf(mx0, __shfl_xor_sync(0xffffffffu, mx0, 2));
        mx1 = fmaxf(mx1, __shfl_xor_sync(0xffffffffu, mx1, 1));
        mx1 = fmaxf(mx1, __shfl_xor_sync(0xffffffffu, mx1, 2));
        float mn0 = fmaxf(m0r, mx0), mn1 = fmaxf(m1r, mx1);
        float al0 = __expf(m0r - mn0), al1 = __expf(m1r - mn1);

        float ls0 = 0.f, ls1 = 0.f;
        uint32_t pa[4][4], pal[4][4];
#pragma unroll
        for (int j = 0; j < 8; j++) {
            float p00 = __expf(sc[j][0] - mn0);
            float p01 = __expf(sc[j][1] - mn0);
            float p10 = __expf(sc[j][2] - mn1);
            float p11 = __expf(sc[j][3] - mn1);
            ls0 += p00 + p01; ls1 += p10 + p11;
            __nv_bfloat16 h00, l00, h01, l01, h10, l10, h11, l11;
            split1(p00, h00, l00); split1(p01, h01, l01);
            split1(p10, h10, l10); split1(p11, h11, l11);
            int kk = j >> 1, hf = (j & 1) << 1;
            pa[kk][hf + 0] = pk(h00, h01);
            pa[kk][hf + 1] = pk(h10, h11);
            pal[kk][hf + 0] = pk(l00, l01);
            pal[kk][hf + 1] = pk(l10, l11);
        }
        ls0 += __shfl_xor_sync(0xffffffffu, ls0, 1);
        ls0 += __shfl_xor_sync(0xffffffffu, ls0, 2);
        ls1 += __shfl_xor_sync(0xffffffffu, ls1, 1);
        ls1 += __shfl_xor_sync(0xffffffffu, ls1, 2);
        l0r = l0r * al0 + ls0;
        l1r = l1r * al1 + ls1;
        m0r = mn0; m1r = mn1;
#pragma unroll
        for (int j = 0; j < 16; j++) {
            o[j][0] *= al0; o[j][1] *= al0;
            o[j][2] *= al1; o[j][3] *= al1;
        }

        // ---- PV (R4 exact: V^T [hd][key], non-trans ldsm) ----
#pragma unroll
        for (int kk = 0; kk < 4; kk++) {
#pragma unroll
            for (int nb = 0; nb < 8; nb++) {
                uint32_t rv = swz(nb * 16 + b_rsub, kk * 32 + b_kh);
                uint32_t vh[4], vl[4];
                ldsm_x4(sb + AVH + rv, vh[0], vh[1], vh[2], vh[3]);
                ldsm_x4(sb + AVL + rv, vl[0], vl[1], vl[2], vl[3]);
                mma_bf16(o[2 * nb + 0], pa[kk], vh + 0);
                mma_bf16(o[2 * nb + 1], pa[kk], vh + 2);
                mma_bf16(o[2 * nb + 0], pal[kk], vh + 0);
                mma_bf16(o[2 * nb + 1], pal[kk], vh + 2);
                mma_bf16(o[2 * nb + 0], pa[kk], vl + 0);
                mma_bf16(o[2 * nb + 1], pa[kk], vl + 2);
            }
        }
    }

    // ---- epilogue (R4 exact, fp32 out) ----
    float inv0 = 1.f / l0r, inv1 = 1.f / l1r;
    int r0 = lane >> 2, c2 = 2 * (lane & 3);
    size_t row0 = (size_t)b * S_ + q0 + wid * 16 + r0;
#pragma unroll
    for (int j = 0; j < 16; j++) {
        int col = h * HD_ + 8 * j + c2;
        float2 v0, v1;
        v0.x = o[j][0] * inv0; v0.y = o[j][1] * inv0;
        v1.x = o[j][2] * inv1; v1.y = o[j][3] * inv1;
        *(float2*)&out[row0 * HID_ + col] = v0;
        *(float2*)&out[(row0 + 8) * HID_ + col] = v1;
    }
}

// ---------------------------------------------------------------------------
// kernel_launch
// ---------------------------------------------------------------------------
extern "C" void kernel_launch(void* const* d_in, const int* in_sizes, int n_in,
                              void* d_out, int out_size)
{
    const float *hidden = nullptr, *cosb = nullptr, *sinb = nullptr;
    const float *wqkv = nullptr, *bqkv = nullptr, *wo = nullptr, *bo = nullptr;
    for (int i = 0; i < n_in; i++) {
        long sz = in_sizes[i];
        const float* p = (const float*)d_in[i];
        if (sz == (long)TOK * HID_)            hidden = p;
        else if (sz == (long)S_ * 64) {
            if (!cosb) cosb = p; else sinb = p;
        }
        else if (sz == (long)HID_ * QKVN)      wqkv = p;
        else if (sz == (long)QKVN)             bqkv = p;
        else if (sz == (long)HID_ * HID_)      wo = p;
        else if (sz == (long)HID_)             bo = p;
    }
    float* out = (float*)d_out;

    float *qkv, *attn;
    __nv_bfloat16 *wqkv_h, *wqkv_l, *wo_h, *wo_l, *qkvb_h, *qkvb_l;
    cudaGetSymbolAddress((void**)&qkv, g_qkv);
    cudaGetSymbolAddress((void**)&attn, g_attn);
    cudaGetSymbolAddress((void**)&wqkv_h, g_wqkv_h);
    cudaGetSymbolAddress((void**)&wqkv_l, g_wqkv_l);
    cudaGetSymbolAddress((void**)&wo_h, g_wo_h);
    cudaGetSymbolAddress((void**)&wo_l, g_wo_l);
    cudaGetSymbolAddress((void**)&qkvb_h, g_qkvb_h);
    cudaGetSymbolAddress((void**)&qkvb_l, g_qkvb_l);

    cudaFuncSetAttribute(gemm3x_kernel,
                         cudaFuncAttributeMaxDynamicSharedMemorySize, GEMM_SMEM);
    cudaFuncSetAttribute(attn_mma_kernel,
                         cudaFuncAttributeMaxDynamicSharedMemorySize, ATTN2_SMEM);

    // 0) weight pre-transpose + split
    {
        dim3 g1(QKVN / 32, HID_ / 32);
        split_wT_kernel<<<g1, 256>>>(wqkv, wqkv_h, wqkv_l, HID_, QKVN);
        dim3 g2(HID_ / 32, HID_ / 32);
        split_wT_kernel<<<g2, 256>>>(wo, wo_h, wo_l, HID_, HID_);
    }
    // 1) QKV projection
    {
        dim3 grid(QKVN / 128, TOK / 128);  // (24, 64)
        gemm3x_kernel<<<grid, 256, GEMM_SMEM>>>(hidden, wqkv_h, wqkv_l,
                                                bqkv, qkv, TOK, QKVN, HID_);
    }
    // 2) RoPE + split (q,k heads)
    {
        int total = TOK * 1280;
        rope_split_kernel<<<total / 256, 256>>>(qkv, cosb, sinb, qkvb_h, qkvb_l);
    }
    // 3) Attention
    {
        dim3 grid(S_ / 128, NH_, B_);  // (16, 16, 4)
        attn_mma_kernel<<<grid, 256, ATTN2_SMEM>>>(qkvb_h, qkvb_l, qkv, attn);
    }
    // 4) Output projection
    {
        dim3 grid(HID_ / 128, TOK / 128);  // (16, 64)
        gemm3x_kernel<<<grid, 256, GEMM_SMEM>>>(attn, wo_h, wo_l,
                                                bo, out, TOK, HID_, HID_);
    }
}

// round 7
// speedup vs baseline: 3.4583x; 1.0709x over previous
#include <cuda_runtime.h>
#include <cuda_bf16.h>
#include <cstdint>
#include <math.h>

// ---------------------------------------------------------------------------
// Problem constants: B=4, S=2048, HID=2048, NH=16, NKV=4, HD=128.
// ---------------------------------------------------------------------------
#define B_    4
#define S_    2048
#define HID_  2048
#define NH_   16
#define NKV_  4
#define HD_   128
#define QSZ   (NH_ * HD_)          // 2048
#define KVSZ  (NKV_ * HD_)         // 512
#define QKVN  (QSZ + 2 * KVSZ)     // 3072
#define TOK   (B_ * S_)            // 8192

// Scratch (device globals; no allocs allowed)
__device__ __align__(16) float          g_qkv[(size_t)TOK * QKVN];
__device__ __align__(16) float          g_attn[(size_t)TOK * HID_];
__device__ __align__(16) __nv_bfloat16  g_hid_h[(size_t)TOK * HID_];
__device__ __align__(16) __nv_bfloat16  g_hid_l[(size_t)TOK * HID_];
__device__ __align__(16) __nv_bfloat16  g_attn_h[(size_t)TOK * HID_];
__device__ __align__(16) __nv_bfloat16  g_attn_l[(size_t)TOK * HID_];
__device__ __align__(16) __nv_bfloat16  g_wqkv_h[(size_t)QKVN * HID_];  // [N][K]
__device__ __align__(16) __nv_bfloat16  g_wqkv_l[(size_t)QKVN * HID_];
__device__ __align__(16) __nv_bfloat16  g_wo_h[(size_t)HID_ * HID_];    // [N][K]
__device__ __align__(16) __nv_bfloat16  g_wo_l[(size_t)HID_ * HID_];
__device__ __align__(16) __nv_bfloat16  g_qkvb_h[(size_t)TOK * QKVN];   // rope'd q,k
__device__ __align__(16) __nv_bfloat16  g_qkvb_l[(size_t)TOK * QKVN];
// V^T pre-transposed: [b][kvh][hd][S]
__device__ __align__(16) __nv_bfloat16  g_vt_h[(size_t)B_ * NKV_ * HD_ * S_];
__device__ __align__(16) __nv_bfloat16  g_vt_l[(size_t)B_ * NKV_ * HD_ * S_];

// ---------------------------------------------------------------------------
// Helpers
// ---------------------------------------------------------------------------
__device__ __forceinline__ uint32_t smem_u32(const void* p) {
    uint32_t a;
    asm("{ .reg .u64 t; cvta.to.shared.u64 t, %1; cvt.u32.u64 %0, t; }"
        : "=r"(a) : "l"(p));
    return a;
}
__device__ __forceinline__ void ldsm_x4(uint32_t addr, uint32_t& r0, uint32_t& r1,
                                        uint32_t& r2, uint32_t& r3) {
    asm volatile("ldmatrix.sync.aligned.m8n8.x4.shared.b16 {%0,%1,%2,%3}, [%4];"
                 : "=r"(r0), "=r"(r1), "=r"(r2), "=r"(r3) : "r"(addr));
}
__device__ __forceinline__ void mma_bf16(float* d, const uint32_t* a,
                                         const uint32_t* b) {
    asm volatile(
        "mma.sync.aligned.m16n8k16.row.col.f32.bf16.bf16.f32 "
        "{%0,%1,%2,%3}, {%4,%5,%6,%7}, {%8,%9}, {%0,%1,%2,%3};"
        : "+f"(d[0]), "+f"(d[1]), "+f"(d[2]), "+f"(d[3])
        : "r"(a[0]), "r"(a[1]), "r"(a[2]), "r"(a[3]), "r"(b[0]), "r"(b[1]));
}
__device__ __forceinline__ uint32_t pk(__nv_bfloat16 a, __nv_bfloat16 b) {
    __nv_bfloat162 t = __halves2bfloat162(a, b);
    return *reinterpret_cast<uint32_t*>(&t);
}
__device__ __forceinline__ void split1(float x, __nv_bfloat16& h, __nv_bfloat16& l) {
    h = __float2bfloat16(x);
    l = __float2bfloat16(x - __bfloat162float(h));
}
// swizzled byte offset, 128-byte rows (64 bf16)
__device__ __forceinline__ uint32_t swz(uint32_t row, uint32_t kbyte) {
    return (row * 128 + kbyte) ^ ((row & 7) << 4);
}
// swizzled byte offset, 256-byte rows (128 bf16)
__device__ __forceinline__ uint32_t swz256(uint32_t row, uint32_t kbyte) {
    return (row * 256 + kbyte) ^ ((row & 7) << 4);
}

// ---------------------------------------------------------------------------
// elementwise fp32 -> bf16 hi/lo (same layout)
// ---------------------------------------------------------------------------
__global__ __launch_bounds__(256) void split_a_kernel(
    const float* __restrict__ A, __nv_bfloat16* __restrict__ Ah,
    __nv_bfloat16* __restrict__ Al, size_t n4)
{
    size_t i = (size_t)blockIdx.x * blockDim.x + threadIdx.x;
    if (i >= n4) return;
    float4 v = *(const float4*)&A[4 * i];
    __nv_bfloat16 h0, h1, h2, h3, l0, l1, l2, l3;
    split1(v.x, h0, l0); split1(v.y, h1, l1);
    split1(v.z, h2, l2); split1(v.w, h3, l3);
    uint2 hv, lv;
    hv.x = pk(h0, h1); hv.y = pk(h2, h3);
    lv.x = pk(l0, l1); lv.y = pk(l2, l3);
    *(uint2*)&Ah[4 * i] = hv;
    *(uint2*)&Al[4 * i] = lv;
}

// ---------------------------------------------------------------------------
// W [K][N] fp32 -> WhT/WlT [N][K] bf16 (tiled transpose + split)
// ---------------------------------------------------------------------------
__global__ __launch_bounds__(256) void split_wT_kernel(
    const float* __restrict__ W, __nv_bfloat16* __restrict__ WhT,
    __nv_bfloat16* __restrict__ WlT, int K, int N)
{
    __shared__ float tile[32][33];
    int nb = blockIdx.x * 32, kb = blockIdx.y * 32;
    int tx = threadIdx.x & 31, ty = threadIdx.x >> 5;   // 32 x 8
#pragma unroll
    for (int r = 0; r < 4; r++)
        tile[ty + 8 * r][tx] = W[(size_t)(kb + ty + 8 * r) * N + nb + tx];
    __syncthreads();
#pragma unroll
    for (int r = 0; r < 4; r++) {
        int n = nb + ty + 8 * r, k = kb + tx;
        float x = tile[tx][ty + 8 * r];
        __nv_bfloat16 h, l;
        split1(x, h, l);
        WhT[(size_t)n * K + k] = h;
        WlT[(size_t)n * K + k] = l;
    }
}

// ---------------------------------------------------------------------------
// V slice of qkv fp32 [tok][...] -> V^T bf16 hi/lo [b][kvh][hd][S]
// ---------------------------------------------------------------------------
__global__ __launch_bounds__(256) void vsplitT_kernel(
    const float* __restrict__ qkv,
    __nv_bfloat16* __restrict__ VtH, __nv_bfloat16* __restrict__ VtL)
{
    __shared__ float tile[32][33];
    int s0 = blockIdx.x * 32;          // seq tile
    int d0 = blockIdx.y * 32;          // hd tile
    int bk = blockIdx.z;               // b * NKV + kvh
    int b  = bk / NKV_, kvh = bk % NKV_;
    int tx = threadIdx.x & 31, ty = threadIdx.x >> 5;

    const float* src = qkv + ((size_t)b * S_) * QKVN + QSZ + KVSZ + kvh * HD_;
#pragma unroll
    for (int r = 0; r < 4; r++) {
        int s = s0 + ty + 8 * r;
        tile[ty + 8 * r][tx] = src[(size_t)s * QKVN + d0 + tx];
    }
    __syncthreads();
#pragma unroll
    for (int r = 0; r < 4; r++) {
        int d = d0 + ty + 8 * r, s = s0 + tx;
        float x = tile[tx][ty + 8 * r];
        __nv_bfloat16 h, l;
        split1(x, h, l);
        size_t o = ((size_t)bk * HD_ + d) * S_ + s;
        VtH[o] = h;
        VtL[o] = l;
    }
}

// ---------------------------------------------------------------------------
// qkv fp32 -> rope'd bf16 hi/lo (q + k heads only)
// ---------------------------------------------------------------------------
__global__ __launch_bounds__(256) void rope_split_kernel(
    const float* __restrict__ qkv,
    const float* __restrict__ cosb, const float* __restrict__ sinb,
    __nv_bfloat16* __restrict__ oh, __nv_bfloat16* __restrict__ ol)
{
    int idx = blockIdx.x * blockDim.x + threadIdx.x;   // TOK * 1280
    int p   = idx % 1280;
    int tok = idx / 1280;
    if (tok >= TOK) return;
    int s = tok & (S_ - 1);
    size_t base = (size_t)tok * QKVN;

    int head = p >> 6, d = p & 63;
    int off = (head < NH_) ? head * HD_ : QSZ + (head - NH_) * HD_;
    float c  = cosb[s * 64 + d];
    float sn = sinb[s * 64 + d];
    float x1 = qkv[base + off + d];
    float x2 = qkv[base + off + d + 64];
    float y1 = x1 * c - x2 * sn;
    float y2 = x2 * c + x1 * sn;
    __nv_bfloat16 h, l;
    split1(y1, h, l);
    oh[base + off + d] = h; ol[base + off + d] = l;
    split1(y2, h, l);
    oh[base + off + d + 64] = h; ol[base + off + d + 64] = l;
}

// ---------------------------------------------------------------------------
// bf16x3 mma.sync GEMM. A pre-split bf16 [M][K]; B pre-split bf16 [N][K].
// Pure LDG->STS producers. Tile 128x128, K-chunk 64, 2 buffers.
// SMEM layouts and consumer identical to R4/R6.
// ---------------------------------------------------------------------------
#define GKC     64
#define STG_B   65536
#define SOFF_AH 0
#define SOFF_AL 16384
#define SOFF_BH 32768
#define SOFF_BL 49152
#define GEMM_SMEM (2 * STG_B)

__global__ __launch_bounds__(256, 1) void gemm3x_kernel(
    const __nv_bfloat16* __restrict__ Ah, const __nv_bfloat16* __restrict__ Al,
    const __nv_bfloat16* __restrict__ BhT, const __nv_bfloat16* __restrict__ BlT,
    const float* __restrict__ bias, float* __restrict__ C,
    int M, int N, int K)
{
    extern __shared__ char smem[];
    const uint32_t sbase = smem_u32(smem);
    const int tid = threadIdx.x;
    const int wid = tid >> 5, lane = tid & 31;
    const int m0 = blockIdx.y * 128, n0 = blockIdx.x * 128;
    const int wm = wid & 3;
    const int wn = wid >> 2;

    const int prow = tid >> 3;   // 0..31, + 32*i
    const int pks  = tid & 7;    // 16B unit within 128B row

    float acc[2][8][4];
#pragma unroll
    for (int i = 0; i < 2; i++)
#pragma unroll
        for (int j = 0; j < 8; j++)
#pragma unroll
            for (int q = 0; q < 4; q++) acc[i][j][q] = 0.f;

    const int NC = K / GKC;

    uint4 ah4[4], al4[4], bh4[4], bl4[4];

    // ---- prologue: LDG chunk 0 ----
#pragma unroll
    for (int i = 0; i < 4; i++) {
        int row = prow + 32 * i;
        size_t ao = (size_t)(m0 + row) * K + pks * 8;
        size_t bo = (size_t)(n0 + row) * K + pks * 8;
        ah4[i] = *(const uint4*)&Ah[ao];
        al4[i] = *(const uint4*)&Al[ao];
        bh4[i] = *(const uint4*)&BhT[bo];
        bl4[i] = *(const uint4*)&BlT[bo];
    }

    const int a_row = wm * 32 + (lane & 15);
    const int a_kh  = (lane >> 4) << 4;
    const int b_row = wn * 64 + ((lane >> 4) << 3) + (lane & 7);
    const int b_kh  = ((lane >> 3) & 1) << 4;

    for (int c = 0; c < NC; c++) {
        const int buf = c & 1;
        char* st = smem + buf * STG_B;

        // ---- direct STS (layouts identical to R4) ----
#pragma unroll
        for (int i = 0; i < 4; i++) {
            int row = prow + 32 * i;
            uint32_t off = swz(row, pks * 16);
            *(uint4*)(st + SOFF_AH + off) = ah4[i];
            *(uint4*)(st + SOFF_AL + off) = al4[i];
            *(uint4*)(st + SOFF_BH + off) = bh4[i];
            *(uint4*)(st + SOFF_BL + off) = bl4[i];
        }
        __syncthreads();

        // ---- LDG chunk c+1 ----
        if (c + 1 < NC) {
            int kc = (c + 1) * GKC;
#pragma unroll
            for (int i = 0; i < 4; i++) {
                int row = prow + 32 * i;
                size_t ao = (size_t)(m0 + row) * K + kc + pks * 8;
                size_t bo = (size_t)(n0 + row) * K + kc + pks * 8;
                ah4[i] = *(const uint4*)&Ah[ao];
                al4[i] = *(const uint4*)&Al[ao];
                bh4[i] = *(const uint4*)&BhT[bo];
                bl4[i] = *(const uint4*)&BlT[bo];
            }
        }

        // ---- compute (identical to R4) ----
        const uint32_t sb = sbase + buf * STG_B;
#pragma unroll
        for (int s = 0; s < 4; s++) {
            const uint32_t kbyte = 32 * s;
            uint32_t ah[2][4], al[2][4];
#pragma unroll
            for (int ti = 0; ti < 2; ti++) {
                uint32_t ra = swz(a_row + 16 * ti, kbyte + a_kh);
                ldsm_x4(sb + SOFF_AH + ra, ah[ti][0], ah[ti][1], ah[ti][2], ah[ti][3]);
                ldsm_x4(sb + SOFF_AL + ra, al[ti][0], al[ti][1], al[ti][2], al[ti][3]);
            }
#pragma unroll
            for (int pj = 0; pj < 4; pj++) {
                uint32_t rb = swz(b_row + 16 * pj, kbyte + b_kh);
                uint32_t bh[4], bl[4];
                ldsm_x4(sb + SOFF_BH + rb, bh[0], bh[1], bh[2], bh[3]);
                ldsm_x4(sb + SOFF_BL + rb, bl[0], bl[1], bl[2], bl[3]);
#pragma unroll
                for (int ti = 0; ti < 2; ti++) {
                    mma_bf16(acc[ti][2 * pj + 0], ah[ti], bh + 0);
                    mma_bf16(acc[ti][2 * pj + 1], ah[ti], bh + 2);
                    mma_bf16(acc[ti][2 * pj + 0], ah[ti], bl + 0);
                    mma_bf16(acc[ti][2 * pj + 1], ah[ti], bl + 2);
                    mma_bf16(acc[ti][2 * pj + 0], al[ti], bh + 0);
                    mma_bf16(acc[ti][2 * pj + 1], al[ti], bh + 2);
                }
            }
        }
        __syncthreads();
    }

    // ---- epilogue (R4) ----
#pragma unroll
    for (int tj = 0; tj < 8; tj++) {
        int col = n0 + wn * 64 + tj * 8 + 2 * (lane & 3);
        float2 bb = *(const float2*)&bias[col];
#pragma unroll
        for (int ti = 0; ti < 2; ti++) {
            int row = m0 + wm * 32 + ti * 16 + (lane >> 2);
            float2 v0, v1;
            v0.x = acc[ti][tj][0] + bb.x; v0.y = acc[ti][tj][1] + bb.y;
            v1.x = acc[ti][tj][2] + bb.x; v1.y = acc[ti][tj][3] + bb.y;
            *(float2*)&C[(size_t)row * N + col] = v0;
            *(float2*)&C[(size_t)(row + 8) * N + col] = v1;
        }
    }
}

// ---------------------------------------------------------------------------
// Tensor-core flash attention. Consumer identical to R4/R6; ALL producers
// are now direct LDG->STS (Q/K from rope-split bf16, V from pre-transposed
// V^T bf16 global).
// ---------------------------------------------------------------------------
#define AQH 0
#define AQL 32768
#define AKH 65536
#define AKL 81920
#define AVH 98304
#define AVL 114688
#define ATTN2_SMEM 131072

__global__ __launch_bounds__(256, 1) void attn_mma_kernel(
    const __nv_bfloat16* __restrict__ qh, const __nv_bfloat16* __restrict__ ql,
    const __nv_bfloat16* __restrict__ vth, const __nv_bfloat16* __restrict__ vtl,
    float* __restrict__ out)
{
    extern __shared__ char sm[];
    const uint32_t sb = smem_u32(sm);
    const int tid = threadIdx.x;
    const int wid = tid >> 5, lane = tid & 31;
    const int q0 = blockIdx.x * 128;
    const int h  = blockIdx.y;
    const int b  = blockIdx.z;
    const int kvh = h >> 2;

    const float scale = 0.08838834764831845f;   // 1/sqrt(128)
    const size_t tok0 = (size_t)b * S_;
    const __nv_bfloat16* qbh = qh + (tok0 + q0) * QKVN + h * HD_;
    const __nv_bfloat16* qbl = ql + (tok0 + q0) * QKVN + h * HD_;
    const __nv_bfloat16* kbh = qh + tok0 * QKVN + QSZ + kvh * HD_;
    const __nv_bfloat16* kbl = ql + tok0 * QKVN + QSZ + kvh * HD_;
    const __nv_bfloat16* vbh = vth + (size_t)(b * NKV_ + kvh) * HD_ * S_;
    const __nv_bfloat16* vbl = vtl + (size_t)(b * NKV_ + kvh) * HD_ * S_;

    // ---- Q: direct STS (layout identical to R4) ----
#pragma unroll
    for (int i = 0; i < 8; i++) {
        int u = tid + 256 * i;
        int row = u >> 4, ks = u & 15;
        uint32_t off = swz256(row, ks * 16);
        *(uint4*)(sm + AQH + off) = *(const uint4*)&qbh[(size_t)row * QKVN + ks * 8];
        *(uint4*)(sm + AQL + off) = *(const uint4*)&qbl[(size_t)row * QKVN + ks * 8];
    }

    // K producer mapping: 64 rows x 256B; V^T: 128 rows x 128B
    const int krow = tid >> 2, kks = tid & 3;    // + i*... 64 rows*16units/256thr = 4 per thread
    const int vrow = tid >> 3, vks = tid & 7;    // 128 rows*8units/256 = 4 per thread

    // ---- prefetch K/V tile 0 ----
    uint4 kh4[4], kl4[4], vh4[4], vl4[4];
#pragma unroll
    for (int i = 0; i < 4; i++) {
        int u = tid + 256 * i;
        int row = u >> 4, ks = u & 15;
        kh4[i] = *(const uint4*)&kbh[(size_t)row * QKVN + ks * 8];
        kl4[i] = *(const uint4*)&kbl[(size_t)row * QKVN + ks * 8];
        int rv = vrow + 32 * i;
        vh4[i] = *(const uint4*)&vbh[(size_t)rv * S_ + vks * 8];
        vl4[i] = *(const uint4*)&vbl[(size_t)rv * S_ + vks * 8];
    }
    (void)krow; (void)kks;

    // accumulators
    float o[16][4];
#pragma unroll
    for (int j = 0; j < 16; j++)
#pragma unroll
        for (int q = 0; q < 4; q++) o[j][q] = 0.f;
    float m0r = -1e30f, m1r = -1e30f, l0r = 0.f, l1r = 0.f;

    // consumer ldmatrix address constants (R4)
    const int a_row = wid * 16 + (lane & 15);
    const int a_kh  = (lane >> 4) << 4;
    const int b_rsub = ((lane >> 4) << 3) + (lane & 7);
    const int b_kh   = ((lane >> 3) & 1) << 4;

    const int NT = S_ / 64;   // 32
    for (int t = 0; t < NT; t++) {
        __syncthreads();  // previous tile's consumers done (covers Q STS too)

        // ---- STS K (256B rows) + V^T (128B rows) — layouts identical to R4 ----
#pragma unroll
        for (int i = 0; i < 4; i++) {
            int u = tid + 256 * i;
            int row = u >> 4, ks = u & 15;
            uint32_t off = swz256(row, ks * 16);
            *(uint4*)(sm + AKH + off) = kh4[i];
            *(uint4*)(sm + AKL + off) = kl4[i];
            int rv = vrow + 32 * i;
            uint32_t vo = swz(rv, vks * 16);
            *(uint4*)(sm + AVH + vo) = vh4[i];
            *(uint4*)(sm + AVL + vo) = vl4[i];
        }
        __syncthreads();

        // ---- prefetch tile t+1 ----
        if (t + 1 < NT) {
            size_t tb = (size_t)(t + 1) * 64;
#pragma unroll
            for (int i = 0; i < 4; i++) {
                int u = tid + 256 * i;
                int row = u >> 4, ks = u & 15;
                kh4[i] = *(const uint4*)&kbh[(tb + row) * QKVN + ks * 8];
                kl4[i] = *(const uint4*)&kbl[(tb + row) * QKVN + ks * 8];
                int rv = vrow + 32 * i;
                vh4[i] = *(const uint4*)&vbh[(size_t)rv * S_ + tb + vks * 8];
                vl4[i] = *(const uint4*)&vbl[(size_t)rv * S_ + tb + vks * 8];
            }
        }

        // ---- QK^T (R4 exact) ----
        float sc[8][4];
#pragma unroll
        for (int j = 0; j < 8; j++)
#pragma unroll
            for (int q = 0; q < 4; q++) sc[j][q] = 0.f;

#pragma unroll
        for (int s = 0; s < 8; s++) {
            uint32_t ra = swz256(a_row, s * 32 + a_kh);
            uint32_t ah[4], al[4];
            ldsm_x4(sb + AQH + ra, ah[0], ah[1], ah[2], ah[3]);
            ldsm_x4(sb + AQL + ra, al[0], al[1], al[2], al[3]);
#pragma unroll
            for (int nb = 0; nb < 4; nb++) {
                uint32_t rb = swz256(nb * 16 + b_rsub, s * 32 + b_kh);
                uint32_t bh[4], bl[4];
                ldsm_x4(sb + AKH + rb, bh[0], bh[1], bh[2], bh[3]);
                ldsm_x4(sb + AKL + rb, bl[0], bl[1], bl[2], bl[3]);
                mma_bf16(sc[2 * nb + 0], ah, bh + 0);
                mma_bf16(sc[2 * nb + 1], ah, bh + 2);
                mma_bf16(sc[2 * nb + 0], ah, bl + 0);
                mma_bf16(sc[2 * nb + 1], ah, bl + 2);
                mma_bf16(sc[2 * nb + 0], al, bh + 0);
                mma_bf16(sc[2 * nb + 1], al, bh + 2);
            }
        }

        // ---- online softmax (R4 exact) ----
        float mx0 = -1e30f, mx1 = -1e30f;
#pragma unroll
        for (int j = 0; j < 8; j++) {
            sc[j][0] *= scale; sc[j][1] *= scale;
            sc[j][2] *= scale; sc[j][3] *= scale;
            mx0 = fmaxf(mx0, fmaxf(sc[j][0], sc[j][1]));
            mx1 = fmaxf(mx1, fmaxf(sc[j][2], sc[j][3]));
        }
        mx0 = fmaxf(mx0, __shfl_xor_sync(0xffffffffu, mx0, 1));
        mx0 = fmaxf(mx0, __shfl_xor_sync(0xffffffffu, mx0, 2));
        mx1 = fmaxf(mx1, __shfl_xor_sync(0xffffffffu, mx1, 1));
        mx1 = fmaxf(mx1, __shfl_xor_sync(0xffffffffu, mx1, 2));
        float mn0 = fmaxf(m0r, mx0), mn1 = fmaxf(m1r, mx1);
        float al0 = __expf(m0r - mn0), al1 = __expf(m1r - mn1);

        float ls0 = 0.f, ls1 = 0.f;
        uint32_t pa[4][4], pal[4][4];
#pragma unroll
        for (int j = 0; j < 8; j++) {
            float p00 = __expf(sc[j][0] - mn0);
            float p01 = __expf(sc[j][1] - mn0);
            float p10 = __expf(sc[j][2] - mn1);
            float p11 = __expf(sc[j][3] - mn1);
            ls0 += p00 + p01; ls1 += p10 + p11;
            __nv_bfloat16 h00, l00, h01, l01, h10, l10, h11, l11;
            split1(p00, h00, l00); split1(p01, h01, l01);
            split1(p10, h10, l10); split1(p11, h11, l11);
            int kk = j >> 1, hf = (j & 1) << 1;
            pa[kk][hf + 0] = pk(h00, h01);
            pa[kk][hf + 1] = pk(h10, h11);
            pal[kk][hf + 0] = pk(l00, l01);
            pal[kk][hf + 1] = pk(l10, l11);
        }
        ls0 += __shfl_xor_sync(0xffffffffu, ls0, 1);
        ls0 += __shfl_xor_sync(0xffffffffu, ls0, 2);
        ls1 += __shfl_xor_sync(0xffffffffu, ls1, 1);
        ls1 += __shfl_xor_sync(0xffffffffu, ls1, 2);
        l0r = l0r * al0 + ls0;
        l1r = l1r * al1 + ls1;
        m0r = mn0; m1r = mn1;
#pragma unroll
        for (int j = 0; j < 16; j++) {
            o[j][0] *= al0; o[j][1] *= al0;
            o[j][2] *= al1; o[j][3] *= al1;
        }

        // ---- PV (R4 exact: V^T [hd][key], non-trans ldsm) ----
#pragma unroll
        for (int kk = 0; kk < 4; kk++) {
#pragma unroll
            for (int nb = 0; nb < 8; nb++) {
                uint32_t rv = swz(nb * 16 + b_rsub, kk * 32 + b_kh);
                uint32_t vh[4], vl[4];
                ldsm_x4(sb + AVH + rv, vh[0], vh[1], vh[2], vh[3]);
                ldsm_x4(sb + AVL + rv, vl[0], vl[1], vl[2], vl[3]);
                mma_bf16(o[2 * nb + 0], pa[kk], vh + 0);
                mma_bf16(o[2 * nb + 1], pa[kk], vh + 2);
                mma_bf16(o[2 * nb + 0], pal[kk], vh + 0);
                mma_bf16(o[2 * nb + 1], pal[kk], vh + 2);
                mma_bf16(o[2 * nb + 0], pa[kk], vl + 0);
                mma_bf16(o[2 * nb + 1], pa[kk], vl + 2);
            }
        }
    }

    // ---- epilogue (R4 exact, fp32 out) ----
    float inv0 = 1.f / l0r, inv1 = 1.f / l1r;
    int r0 = lane >> 2, c2 = 2 * (lane & 3);
    size_t row0 = (size_t)b * S_ + q0 + wid * 16 + r0;
#pragma unroll
    for (int j = 0; j < 16; j++) {
        int col = h * HD_ + 8 * j + c2;
        float2 v0, v1;
        v0.x = o[j][0] * inv0; v0.y = o[j][1] * inv0;
        v1.x = o[j][2] * inv1; v1.y = o[j][3] * inv1;
        *(float2*)&out[row0 * HID_ + col] = v0;
        *(float2*)&out[(row0 + 8) * HID_ + col] = v1;
    }
}

// ---------------------------------------------------------------------------
// kernel_launch
// ---------------------------------------------------------------------------
extern "C" void kernel_launch(void* const* d_in, const int* in_sizes, int n_in,
                              void* d_out, int out_size)
{
    const float *hidden = nullptr, *cosb = nullptr, *sinb = nullptr;
    const float *wqkv = nullptr, *bqkv = nullptr, *wo = nullptr, *bo = nullptr;
    for (int i = 0; i < n_in; i++) {
        long sz = in_sizes[i];
        const float* p = (const float*)d_in[i];
        if (sz == (long)TOK * HID_)            hidden = p;
        else if (sz == (long)S_ * 64) {
            if (!cosb) cosb = p; else sinb = p;
        }
        else if (sz == (long)HID_ * QKVN)      wqkv = p;
        else if (sz == (long)QKVN)             bqkv = p;
        else if (sz == (long)HID_ * HID_)      wo = p;
        else if (sz == (long)HID_)             bo = p;
    }
    float* out = (float*)d_out;

    float *qkv, *attn;
    __nv_bfloat16 *hid_h, *hid_l, *attn_h, *attn_l;
    __nv_bfloat16 *wqkv_h, *wqkv_l, *wo_h, *wo_l, *qkvb_h, *qkvb_l;
    __nv_bfloat16 *vt_h, *vt_l;
    cudaGetSymbolAddress((void**)&qkv, g_qkv);
    cudaGetSymbolAddress((void**)&attn, g_attn);
    cudaGetSymbolAddress((void**)&hid_h, g_hid_h);
    cudaGetSymbolAddress((void**)&hid_l, g_hid_l);
    cudaGetSymbolAddress((void**)&attn_h, g_attn_h);
    cudaGetSymbolAddress((void**)&attn_l, g_attn_l);
    cudaGetSymbolAddress((void**)&wqkv_h, g_wqkv_h);
    cudaGetSymbolAddress((void**)&wqkv_l, g_wqkv_l);
    cudaGetSymbolAddress((void**)&wo_h, g_wo_h);
    cudaGetSymbolAddress((void**)&wo_l, g_wo_l);
    cudaGetSymbolAddress((void**)&qkvb_h, g_qkvb_h);
    cudaGetSymbolAddress((void**)&qkvb_l, g_qkvb_l);
    cudaGetSymbolAddress((void**)&vt_h, g_vt_h);
    cudaGetSymbolAddress((void**)&vt_l, g_vt_l);

    cudaFuncSetAttribute(gemm3x_kernel,
                         cudaFuncAttributeMaxDynamicSharedMemorySize, GEMM_SMEM);
    cudaFuncSetAttribute(attn_mma_kernel,
                         cudaFuncAttributeMaxDynamicSharedMemorySize, ATTN2_SMEM);

    // 0) weight + hidden pre-split
    {
        dim3 g1(QKVN / 32, HID_ / 32);
        split_wT_kernel<<<g1, 256>>>(wqkv, wqkv_h, wqkv_l, HID_, QKVN);
        dim3 g2(HID_ / 32, HID_ / 32);
        split_wT_kernel<<<g2, 256>>>(wo, wo_h, wo_l, HID_, HID_);
        size_t n4 = (size_t)TOK * HID_ / 4;
        split_a_kernel<<<(unsigned)((n4 + 255) / 256), 256>>>(hidden, hid_h, hid_l, n4);
    }
    // 1) QKV projection
    {
        dim3 grid(QKVN / 128, TOK / 128);  // (24, 64)
        gemm3x_kernel<<<grid, 256, GEMM_SMEM>>>(hid_h, hid_l, wqkv_h, wqkv_l,
                                                bqkv, qkv, TOK, QKVN, HID_);
    }
    // 2) RoPE + split (q,k) and V transpose + split
    {
        int total = TOK * 1280;
        rope_split_kernel<<<total / 256, 256>>>(qkv, cosb, sinb, qkvb_h, qkvb_l);
        dim3 gv(S_ / 32, HD_ / 32, B_ * NKV_);
        vsplitT_kernel<<<gv, 256>>>(qkv, vt_h, vt_l);
    }
    // 3) Attention
    {
        dim3 grid(S_ / 128, NH_, B_);  // (16, 16, 4)
        attn_mma_kernel<<<grid, 256, ATTN2_SMEM>>>(qkvb_h, qkvb_l, vt_h, vt_l, attn);
    }
    // 3.5) split attention output for out-proj A operand
    {
        size_t n4 = (size_t)TOK * HID_ / 4;
        split_a_kernel<<<(unsigned)((n4 + 255) / 256), 256>>>(attn, attn_h, attn_l, n4);
    }
    // 4) Output projection
    {
        dim3 grid(HID_ / 128, TOK / 128);  // (16, 64)
        gemm3x_kernel<<<grid, 256, GEMM_SMEM>>>(attn_h, attn_l, wo_h, wo_l,
                                                bo, out, TOK, HID_, HID_);
    }
}

// round 8
// speedup vs baseline: 3.7247x; 1.0770x over previous
#include <cuda_runtime.h>
#include <cuda_bf16.h>
#include <cstdint>
#include <math.h>

// ---------------------------------------------------------------------------
// Problem constants: B=4, S=2048, HID=2048, NH=16, NKV=4, HD=128.
// ---------------------------------------------------------------------------
#define B_    4
#define S_    2048
#define HID_  2048
#define NH_   16
#define NKV_  4
#define HD_   128
#define QSZ   (NH_ * HD_)          // 2048
#define KVSZ  (NKV_ * HD_)         // 512
#define QKVN  (QSZ + 2 * KVSZ)     // 3072
#define TOK   (B_ * S_)            // 8192

// Scratch (device globals; no allocs allowed)
__device__ __align__(16) float          g_qkv[(size_t)TOK * QKVN];
__device__ __align__(16) float          g_attn[(size_t)TOK * HID_];
__device__ __align__(16) __nv_bfloat16  g_hid_h[(size_t)TOK * HID_];
__device__ __align__(16) __nv_bfloat16  g_hid_l[(size_t)TOK * HID_];
__device__ __align__(16) __nv_bfloat16  g_attn_h[(size_t)TOK * HID_];
__device__ __align__(16) __nv_bfloat16  g_attn_l[(size_t)TOK * HID_];
__device__ __align__(16) __nv_bfloat16  g_wqkv_h[(size_t)QKVN * HID_];  // [N][K]
__device__ __align__(16) __nv_bfloat16  g_wqkv_l[(size_t)QKVN * HID_];
__device__ __align__(16) __nv_bfloat16  g_wo_h[(size_t)HID_ * HID_];    // [N][K]
__device__ __align__(16) __nv_bfloat16  g_wo_l[(size_t)HID_ * HID_];
__device__ __align__(16) __nv_bfloat16  g_qkvb_h[(size_t)TOK * QKVN];   // rope'd q,k
__device__ __align__(16) __nv_bfloat16  g_qkvb_l[(size_t)TOK * QKVN];
// V^T pre-transposed: [b][kvh][hd][S]
__device__ __align__(16) __nv_bfloat16  g_vt_h[(size_t)B_ * NKV_ * HD_ * S_];
__device__ __align__(16) __nv_bfloat16  g_vt_l[(size_t)B_ * NKV_ * HD_ * S_];

// ---------------------------------------------------------------------------
// Helpers
// ---------------------------------------------------------------------------
__device__ __forceinline__ uint32_t smem_u32(const void* p) {
    uint32_t a;
    asm("{ .reg .u64 t; cvta.to.shared.u64 t, %1; cvt.u32.u64 %0, t; }"
        : "=r"(a) : "l"(p));
    return a;
}
__device__ __forceinline__ void ldsm_x4(uint32_t addr, uint32_t& r0, uint32_t& r1,
                                        uint32_t& r2, uint32_t& r3) {
    asm volatile("ldmatrix.sync.aligned.m8n8.x4.shared.b16 {%0,%1,%2,%3}, [%4];"
                 : "=r"(r0), "=r"(r1), "=r"(r2), "=r"(r3) : "r"(addr));
}
__device__ __forceinline__ void mma_bf16(float* d, const uint32_t* a,
                                         const uint32_t* b) {
    asm volatile(
        "mma.sync.aligned.m16n8k16.row.col.f32.bf16.bf16.f32 "
        "{%0,%1,%2,%3}, {%4,%5,%6,%7}, {%8,%9}, {%0,%1,%2,%3};"
        : "+f"(d[0]), "+f"(d[1]), "+f"(d[2]), "+f"(d[3])
        : "r"(a[0]), "r"(a[1]), "r"(a[2]), "r"(a[3]), "r"(b[0]), "r"(b[1]));
}
__device__ __forceinline__ uint32_t pk(__nv_bfloat16 a, __nv_bfloat16 b) {
    __nv_bfloat162 t = __halves2bfloat162(a, b);
    return *reinterpret_cast<uint32_t*>(&t);
}
__device__ __forceinline__ void split1(float x, __nv_bfloat16& h, __nv_bfloat16& l) {
    h = __float2bfloat16(x);
    l = __float2bfloat16(x - __bfloat162float(h));
}
// swizzled byte offset, 128-byte rows (64 bf16)
__device__ __forceinline__ uint32_t swz(uint32_t row, uint32_t kbyte) {
    return (row * 128 + kbyte) ^ ((row & 7) << 4);
}
// swizzled byte offset, 256-byte rows (128 bf16)
__device__ __forceinline__ uint32_t swz256(uint32_t row, uint32_t kbyte) {
    return (row * 256 + kbyte) ^ ((row & 7) << 4);
}

// ---------------------------------------------------------------------------
// elementwise fp32 -> bf16 hi/lo (same layout)
// ---------------------------------------------------------------------------
__global__ __launch_bounds__(256) void split_a_kernel(
    const float* __restrict__ A, __nv_bfloat16* __restrict__ Ah,
    __nv_bfloat16* __restrict__ Al, size_t n4)
{
    size_t i = (size_t)blockIdx.x * blockDim.x + threadIdx.x;
    if (i >= n4) return;
    float4 v = *(const float4*)&A[4 * i];
    __nv_bfloat16 h0, h1, h2, h3, l0, l1, l2, l3;
    split1(v.x, h0, l0); split1(v.y, h1, l1);
    split1(v.z, h2, l2); split1(v.w, h3, l3);
    uint2 hv, lv;
    hv.x = pk(h0, h1); hv.y = pk(h2, h3);
    lv.x = pk(l0, l1); lv.y = pk(l2, l3);
    *(uint2*)&Ah[4 * i] = hv;
    *(uint2*)&Al[4 * i] = lv;
}

// ---------------------------------------------------------------------------
// W [K][N] fp32 -> WhT/WlT [N][K] bf16 (tiled transpose + split)
// ---------------------------------------------------------------------------
__global__ __launch_bounds__(256) void split_wT_kernel(
    const float* __restrict__ W, __nv_bfloat16* __restrict__ WhT,
    __nv_bfloat16* __restrict__ WlT, int K, int N)
{
    __shared__ float tile[32][33];
    int nb = blockIdx.x * 32, kb = blockIdx.y * 32;
    int tx = threadIdx.x & 31, ty = threadIdx.x >> 5;   // 32 x 8
#pragma unroll
    for (int r = 0; r < 4; r++)
        tile[ty + 8 * r][tx] = W[(size_t)(kb + ty + 8 * r) * N + nb + tx];
    __syncthreads();
#pragma unroll
    for (int r = 0; r < 4; r++) {
        int n = nb + ty + 8 * r, k = kb + tx;
        float x = tile[tx][ty + 8 * r];
        __nv_bfloat16 h, l;
        split1(x, h, l);
        WhT[(size_t)n * K + k] = h;
        WlT[(size_t)n * K + k] = l;
    }
}

// ---------------------------------------------------------------------------
// V slice of qkv fp32 [tok][...] -> V^T bf16 hi/lo [b][kvh][hd][S]
// ---------------------------------------------------------------------------
__global__ __launch_bounds__(256) void vsplitT_kernel(
    const float* __restrict__ qkv,
    __nv_bfloat16* __restrict__ VtH, __nv_bfloat16* __restrict__ VtL)
{
    __shared__ float tile[32][33];
    int s0 = blockIdx.x * 32;          // seq tile
    int d0 = blockIdx.y * 32;          // hd tile
    int bk = blockIdx.z;               // b * NKV + kvh
    int b  = bk / NKV_, kvh = bk % NKV_;
    int tx = threadIdx.x & 31, ty = threadIdx.x >> 5;

    const float* src = qkv + ((size_t)b * S_) * QKVN + QSZ + KVSZ + kvh * HD_;
#pragma unroll
    for (int r = 0; r < 4; r++) {
        int s = s0 + ty + 8 * r;
        tile[ty + 8 * r][tx] = src[(size_t)s * QKVN + d0 + tx];
    }
    __syncthreads();
#pragma unroll
    for (int r = 0; r < 4; r++) {
        int d = d0 + ty + 8 * r, s = s0 + tx;
        float x = tile[tx][ty + 8 * r];
        __nv_bfloat16 h, l;
        split1(x, h, l);
        size_t o = ((size_t)bk * HD_ + d) * S_ + s;
        VtH[o] = h;
        VtL[o] = l;
    }
}

// ---------------------------------------------------------------------------
// qkv fp32 -> rope'd bf16 hi/lo (q + k heads only)
// ---------------------------------------------------------------------------
__global__ __launch_bounds__(256) void rope_split_kernel(
    const float* __restrict__ qkv,
    const float* __restrict__ cosb, const float* __restrict__ sinb,
    __nv_bfloat16* __restrict__ oh, __nv_bfloat16* __restrict__ ol)
{
    int idx = blockIdx.x * blockDim.x + threadIdx.x;   // TOK * 1280
    int p   = idx % 1280;
    int tok = idx / 1280;
    if (tok >= TOK) return;
    int s = tok & (S_ - 1);
    size_t base = (size_t)tok * QKVN;

    int head = p >> 6, d = p & 63;
    int off = (head < NH_) ? head * HD_ : QSZ + (head - NH_) * HD_;
    float c  = cosb[s * 64 + d];
    float sn = sinb[s * 64 + d];
    float x1 = qkv[base + off + d];
    float x2 = qkv[base + off + d + 64];
    float y1 = x1 * c - x2 * sn;
    float y2 = x2 * c + x1 * sn;
    __nv_bfloat16 h, l;
    split1(y1, h, l);
    oh[base + off + d] = h; ol[base + off + d] = l;
    split1(y2, h, l);
    oh[base + off + d + 64] = h; ol[base + off + d + 64] = l;
}

// ---------------------------------------------------------------------------
// bf16x3 mma.sync GEMM. Pure LDG->STS producers, SINGLE sync per chunk
// (sync #2 removed: STS(c) targets buf c%2 whose readers [compute(c-2)]
//  are fenced by iteration c-1's barrier; compute(c-1) reads the other buf).
// SMEM layouts and consumer identical to R7.
// ---------------------------------------------------------------------------
#define GKC     64
#define STG_B   65536
#define SOFF_AH 0
#define SOFF_AL 16384
#define SOFF_BH 32768
#define SOFF_BL 49152
#define GEMM_SMEM (2 * STG_B)

__global__ __launch_bounds__(256, 1) void gemm3x_kernel(
    const __nv_bfloat16* __restrict__ Ah, const __nv_bfloat16* __restrict__ Al,
    const __nv_bfloat16* __restrict__ BhT, const __nv_bfloat16* __restrict__ BlT,
    const float* __restrict__ bias, float* __restrict__ C,
    int M, int N, int K)
{
    extern __shared__ char smem[];
    const uint32_t sbase = smem_u32(smem);
    const int tid = threadIdx.x;
    const int wid = tid >> 5, lane = tid & 31;
    const int m0 = blockIdx.y * 128, n0 = blockIdx.x * 128;
    const int wm = wid & 3;
    const int wn = wid >> 2;

    const int prow = tid >> 3;   // 0..31, + 32*i
    const int pks  = tid & 7;    // 16B unit within 128B row

    float acc[2][8][4];
#pragma unroll
    for (int i = 0; i < 2; i++)
#pragma unroll
        for (int j = 0; j < 8; j++)
#pragma unroll
            for (int q = 0; q < 4; q++) acc[i][j][q] = 0.f;

    const int NC = K / GKC;

    uint4 ah4[4], al4[4], bh4[4], bl4[4];

    // ---- prologue: LDG chunk 0 ----
#pragma unroll
    for (int i = 0; i < 4; i++) {
        int row = prow + 32 * i;
        size_t ao = (size_t)(m0 + row) * K + pks * 8;
        size_t bo = (size_t)(n0 + row) * K + pks * 8;
        ah4[i] = *(const uint4*)&Ah[ao];
        al4[i] = *(const uint4*)&Al[ao];
        bh4[i] = *(const uint4*)&BhT[bo];
        bl4[i] = *(const uint4*)&BlT[bo];
    }

    const int a_row = wm * 32 + (lane & 15);
    const int a_kh  = (lane >> 4) << 4;
    const int b_row = wn * 64 + ((lane >> 4) << 3) + (lane & 7);
    const int b_kh  = ((lane >> 3) & 1) << 4;

    for (int c = 0; c < NC; c++) {
        const int buf = c & 1;
        char* st = smem + buf * STG_B;

        // ---- STS(c) ----
#pragma unroll
        for (int i = 0; i < 4; i++) {
            int row = prow + 32 * i;
            uint32_t off = swz(row, pks * 16);
            *(uint4*)(st + SOFF_AH + off) = ah4[i];
            *(uint4*)(st + SOFF_AL + off) = al4[i];
            *(uint4*)(st + SOFF_BH + off) = bh4[i];
            *(uint4*)(st + SOFF_BL + off) = bl4[i];
        }
        __syncthreads();   // single barrier per chunk

        // ---- LDG(c+1) ----
        if (c + 1 < NC) {
            int kc = (c + 1) * GKC;
#pragma unroll
            for (int i = 0; i < 4; i++) {
                int row = prow + 32 * i;
                size_t ao = (size_t)(m0 + row) * K + kc + pks * 8;
                size_t bo = (size_t)(n0 + row) * K + kc + pks * 8;
                ah4[i] = *(const uint4*)&Ah[ao];
                al4[i] = *(const uint4*)&Al[ao];
                bh4[i] = *(const uint4*)&BhT[bo];
                bl4[i] = *(const uint4*)&BlT[bo];
            }
        }

        // ---- compute(c) (identical to R7) ----
        const uint32_t sb = sbase + buf * STG_B;
#pragma unroll
        for (int s = 0; s < 4; s++) {
            const uint32_t kbyte = 32 * s;
            uint32_t ah[2][4], al[2][4];
#pragma unroll
            for (int ti = 0; ti < 2; ti++) {
                uint32_t ra = swz(a_row + 16 * ti, kbyte + a_kh);
                ldsm_x4(sb + SOFF_AH + ra, ah[ti][0], ah[ti][1], ah[ti][2], ah[ti][3]);
                ldsm_x4(sb + SOFF_AL + ra, al[ti][0], al[ti][1], al[ti][2], al[ti][3]);
            }
#pragma unroll
            for (int pj = 0; pj < 4; pj++) {
                uint32_t rb = swz(b_row + 16 * pj, kbyte + b_kh);
                uint32_t bh[4], bl[4];
                ldsm_x4(sb + SOFF_BH + rb, bh[0], bh[1], bh[2], bh[3]);
                ldsm_x4(sb + SOFF_BL + rb, bl[0], bl[1], bl[2], bl[3]);
#pragma unroll
                for (int ti = 0; ti < 2; ti++) {
                    mma_bf16(acc[ti][2 * pj + 0], ah[ti], bh + 0);
                    mma_bf16(acc[ti][2 * pj + 1], ah[ti], bh + 2);
                    mma_bf16(acc[ti][2 * pj + 0], ah[ti], bl + 0);
                    mma_bf16(acc[ti][2 * pj + 1], ah[ti], bl + 2);
                    mma_bf16(acc[ti][2 * pj + 0], al[ti], bh + 0);
                    mma_bf16(acc[ti][2 * pj + 1], al[ti], bh + 2);
                }
            }
        }
    }

    // ---- epilogue (R7) ----
#pragma unroll
    for (int tj = 0; tj < 8; tj++) {
        int col = n0 + wn * 64 + tj * 8 + 2 * (lane & 3);
        float2 bb = *(const float2*)&bias[col];
#pragma unroll
        for (int ti = 0; ti < 2; ti++) {
            int row = m0 + wm * 32 + ti * 16 + (lane >> 2);
            float2 v0, v1;
            v0.x = acc[ti][tj][0] + bb.x; v0.y = acc[ti][tj][1] + bb.y;
            v1.x = acc[ti][tj][2] + bb.x; v1.y = acc[ti][tj][3] + bb.y;
            *(float2*)&C[(size_t)row * N + col] = v0;
            *(float2*)&C[(size_t)(row + 8) * N + col] = v1;
        }
    }
}

// ---------------------------------------------------------------------------
// Tensor-core flash attention. Consumer identical to R7; KV is now DOUBLE
// buffered (Q 64KB + 2x64KB KV = 192KB) enabling a single sync per tile
// with the same proof as the GEMM.
// ---------------------------------------------------------------------------
#define AQH  0
#define AQL  32768
#define AKV0 65536
#define ABUF 65536
#define AKH  0
#define AKL  16384
#define AVH  32768
#define AVL  49152
#define ATTN2_SMEM (65536 + 2 * ABUF)

__global__ __launch_bounds__(256, 1) void attn_mma_kernel(
    const __nv_bfloat16* __restrict__ qh, const __nv_bfloat16* __restrict__ ql,
    const __nv_bfloat16* __restrict__ vth, const __nv_bfloat16* __restrict__ vtl,
    float* __restrict__ out)
{
    extern __shared__ char sm[];
    const uint32_t sb = smem_u32(sm);
    const int tid = threadIdx.x;
    const int wid = tid >> 5, lane = tid & 31;
    const int q0 = blockIdx.x * 128;
    const int h  = blockIdx.y;
    const int b  = blockIdx.z;
    const int kvh = h >> 2;

    const float scale = 0.08838834764831845f;   // 1/sqrt(128)
    const size_t tok0 = (size_t)b * S_;
    const __nv_bfloat16* qbh = qh + (tok0 + q0) * QKVN + h * HD_;
    const __nv_bfloat16* qbl = ql + (tok0 + q0) * QKVN + h * HD_;
    const __nv_bfloat16* kbh = qh + tok0 * QKVN + QSZ + kvh * HD_;
    const __nv_bfloat16* kbl = ql + tok0 * QKVN + QSZ + kvh * HD_;
    const __nv_bfloat16* vbh = vth + (size_t)(b * NKV_ + kvh) * HD_ * S_;
    const __nv_bfloat16* vbl = vtl + (size_t)(b * NKV_ + kvh) * HD_ * S_;

    // ---- Q: direct STS (layout identical to R7) ----
#pragma unroll
    for (int i = 0; i < 8; i++) {
        int u = tid + 256 * i;
        int row = u >> 4, ks = u & 15;
        uint32_t off = swz256(row, ks * 16);
        *(uint4*)(sm + AQH + off) = *(const uint4*)&qbh[(size_t)row * QKVN + ks * 8];
        *(uint4*)(sm + AQL + off) = *(const uint4*)&qbl[(size_t)row * QKVN + ks * 8];
    }

    const int vrow = tid >> 3, vks = tid & 7;    // V^T: 128 rows x 8 units

    // ---- prologue: LDG tile 0 into registers ----
    uint4 kh4[4], kl4[4], vh4[4], vl4[4];
#pragma unroll
    for (int i = 0; i < 4; i++) {
        int u = tid + 256 * i;
        int row = u >> 4, ks = u & 15;
        kh4[i] = *(const uint4*)&kbh[(size_t)row * QKVN + ks * 8];
        kl4[i] = *(const uint4*)&kbl[(size_t)row * QKVN + ks * 8];
        int rv = vrow + 32 * i;
        vh4[i] = *(const uint4*)&vbh[(size_t)rv * S_ + vks * 8];
        vl4[i] = *(const uint4*)&vbl[(size_t)rv * S_ + vks * 8];
    }

    // accumulators
    float o[16][4];
#pragma unroll
    for (int j = 0; j < 16; j++)
#pragma unroll
        for (int q = 0; q < 4; q++) o[j][q] = 0.f;
    float m0r = -1e30f, m1r = -1e30f, l0r = 0.f, l1r = 0.f;

    // consumer ldmatrix address constants (R7)
    const int a_row = wid * 16 + (lane & 15);
    const int a_kh  = (lane >> 4) << 4;
    const int b_rsub = ((lane >> 4) << 3) + (lane & 7);
    const int b_kh   = ((lane >> 3) & 1) << 4;

    const int NT = S_ / 64;   // 32
    for (int t = 0; t < NT; t++) {
        char* kvs = sm + AKV0 + (t & 1) * ABUF;

        // ---- STS(t) into KV buf t&1 ----
#pragma unroll
        for (int i = 0; i < 4; i++) {
            int u = tid + 256 * i;
            int row = u >> 4, ks = u & 15;
            uint32_t off = swz256(row, ks * 16);
            *(uint4*)(kvs + AKH + off) = kh4[i];
            *(uint4*)(kvs + AKL + off) = kl4[i];
            int rv = vrow + 32 * i;
            uint32_t vo = swz(rv, vks * 16);
            *(uint4*)(kvs + AVH + vo) = vh4[i];
            *(uint4*)(kvs + AVL + vo) = vl4[i];
        }
        __syncthreads();   // single barrier per tile (also covers Q STS at t=0)

        // ---- LDG(t+1) ----
        if (t + 1 < NT) {
            size_t tb = (size_t)(t + 1) * 64;
#pragma unroll
            for (int i = 0; i < 4; i++) {
                int u = tid + 256 * i;
                int row = u >> 4, ks = u & 15;
                kh4[i] = *(const uint4*)&kbh[(tb + row) * QKVN + ks * 8];
                kl4[i] = *(const uint4*)&kbl[(tb + row) * QKVN + ks * 8];
                int rv = vrow + 32 * i;
                vh4[i] = *(const uint4*)&vbh[(size_t)rv * S_ + tb + vks * 8];
                vl4[i] = *(const uint4*)&vbl[(size_t)rv * S_ + tb + vks * 8];
            }
        }

        const uint32_t kvb = sb + AKV0 + (t & 1) * ABUF;

        // ---- QK^T (R7 exact) ----
        float sc[8][4];
#pragma unroll
        for (int j = 0; j < 8; j++)
#pragma unroll
            for (int q = 0; q < 4; q++) sc[j][q] = 0.f;

#pragma unroll
        for (int s = 0; s < 8; s++) {
            uint32_t ra = swz256(a_row, s * 32 + a_kh);
            uint32_t ah[4], al[4];
            ldsm_x4(sb + AQH + ra, ah[0], ah[1], ah[2], ah[3]);
            ldsm_x4(sb + AQL + ra, al[0], al[1], al[2], al[3]);
#pragma unroll
            for (int nb = 0; nb < 4; nb++) {
                uint32_t rb = swz256(nb * 16 + b_rsub, s * 32 + b_kh);
                uint32_t bh[4], bl[4];
                ldsm_x4(kvb + AKH + rb, bh[0], bh[1], bh[2], bh[3]);
                ldsm_x4(kvb + AKL + rb, bl[0], bl[1], bl[2], bl[3]);
                mma_bf16(sc[2 * nb + 0], ah, bh + 0);
                mma_bf16(sc[2 * nb + 1], ah, bh + 2);
                mma_bf16(sc[2 * nb + 0], ah, bl + 0);
                mma_bf16(sc[2 * nb + 1], ah, bl + 2);
                mma_bf16(sc[2 * nb + 0], al, bh + 0);
                mma_bf16(sc[2 * nb + 1], al, bh + 2);
            }
        }

        // ---- online softmax (R7 exact) ----
        float mx0 = -1e30f, mx1 = -1e30f;
#pragma unroll
        for (int j = 0; j < 8; j++) {
            sc[j][0] *= scale; sc[j][1] *= scale;
            sc[j][2] *= scale; sc[j][3] *= scale;
            mx0 = fmaxf(mx0, fmaxf(sc[j][0], sc[j][1]));
            mx1 = fmaxf(mx1, fmaxf(sc[j][2], sc[j][3]));
        }
        mx0 = fmaxf(mx0, __shfl_xor_sync(0xffffffffu, mx0, 1));
        mx0 = fmaxf(mx0, __shfl_xor_sync(0xffffffffu, mx0, 2));
        mx1 = fmaxf(mx1, __shfl_xor_sync(0xffffffffu, mx1, 1));
        mx1 = fmaxf(mx1, __shfl_xor_sync(0xffffffffu, mx1, 2));
        float mn0 = fmaxf(m0r, mx0), mn1 = fmaxf(m1r, mx1);
        float al0 = __expf(m0r - mn0), al1 = __expf(m1r - mn1);

        float ls0 = 0.f, ls1 = 0.f;
        uint32_t pa[4][4], pal[4][4];
#pragma unroll
        for (int j = 0; j < 8; j++) {
            float p00 = __expf(sc[j][0] - mn0);
            float p01 = __expf(sc[j][1] - mn0);
            float p10 = __expf(sc[j][2] - mn1);
            float p11 = __expf(sc[j][3] - mn1);
            ls0 += p00 + p01; ls1 += p10 + p11;
            __nv_bfloat16 h00, l00, h01, l01, h10, l10, h11, l11;
            split1(p00, h00, l00); split1(p01, h01, l01);
            split1(p10, h10, l10); split1(p11, h11, l11);
            int kk = j >> 1, hf = (j & 1) << 1;
            pa[kk][hf + 0] = pk(h00, h01);
            pa[kk][hf + 1] = pk(h10, h11);
            pal[kk][hf + 0] = pk(l00, l01);
            pal[kk][hf + 1] = pk(l10, l11);
        }
        ls0 += __shfl_xor_sync(0xffffffffu, ls0, 1);
        ls0 += __shfl_xor_sync(0xffffffffu, ls0, 2);
        ls1 += __shfl_xor_sync(0xffffffffu, ls1, 1);
        ls1 += __shfl_xor_sync(0xffffffffu, ls1, 2);
        l0r = l0r * al0 + ls0;
        l1r = l1r * al1 + ls1;
        m0r = mn0; m1r = mn1;
#pragma unroll
        for (int j = 0; j < 16; j++) {
            o[j][0] *= al0; o[j][1] *= al0;
            o[j][2] *= al1; o[j][3] *= al1;
        }

        // ---- PV (R7 exact) ----
#pragma unroll
        for (int kk = 0; kk < 4; kk++) {
#pragma unroll
            for (int nb = 0; nb < 8; nb++) {
                uint32_t rv = swz(nb * 16 + b_rsub, kk * 32 + b_kh);
                uint32_t vh[4], vl[4];
                ldsm_x4(kvb + AVH + rv, vh[0], vh[1], vh[2], vh[3]);
                ldsm_x4(kvb + AVL + rv, vl[0], vl[1], vl[2], vl[3]);
                mma_bf16(o[2 * nb + 0], pa[kk], vh + 0);
                mma_bf16(o[2 * nb + 1], pa[kk], vh + 2);
                mma_bf16(o[2 * nb + 0], pal[kk], vh + 0);
                mma_bf16(o[2 * nb + 1], pal[kk], vh + 2);
                mma_bf16(o[2 * nb + 0], pa[kk], vl + 0);
                mma_bf16(o[2 * nb + 1], pa[kk], vl + 2);
            }
        }
    }

    // ---- epilogue (R7 exact, fp32 out) ----
    float inv0 = 1.f / l0r, inv1 = 1.f / l1r;
    int r0 = lane >> 2, c2 = 2 * (lane & 3);
    size_t row0 = (size_t)b * S_ + q0 + wid * 16 + r0;
#pragma unroll
    for (int j = 0; j < 16; j++) {
        int col = h * HD_ + 8 * j + c2;
        float2 v0, v1;
        v0.x = o[j][0] * inv0; v0.y = o[j][1] * inv0;
        v1.x = o[j][2] * inv1; v1.y = o[j][3] * inv1;
        *(float2*)&out[row0 * HID_ + col] = v0;
        *(float2*)&out[(row0 + 8) * HID_ + col] = v1;
    }
}

// ---------------------------------------------------------------------------
// kernel_launch
// ---------------------------------------------------------------------------
extern "C" void kernel_launch(void* const* d_in, const int* in_sizes, int n_in,
                              void* d_out, int out_size)
{
    const float *hidden = nullptr, *cosb = nullptr, *sinb = nullptr;
    const float *wqkv = nullptr, *bqkv = nullptr, *wo = nullptr, *bo = nullptr;
    for (int i = 0; i < n_in; i++) {
        long sz = in_sizes[i];
        const float* p = (const float*)d_in[i];
        if (sz == (long)TOK * HID_)            hidden = p;
        else if (sz == (long)S_ * 64) {
            if (!cosb) cosb = p; else sinb = p;
        }
        else if (sz == (long)HID_ * QKVN)      wqkv = p;
        else if (sz == (long)QKVN)             bqkv = p;
        else if (sz == (long)HID_ * HID_)      wo = p;
        else if (sz == (long)HID_)             bo = p;
    }
    float* out = (float*)d_out;

    float *qkv, *attn;
    __nv_bfloat16 *hid_h, *hid_l, *attn_h, *attn_l;
    __nv_bfloat16 *wqkv_h, *wqkv_l, *wo_h, *wo_l, *qkvb_h, *qkvb_l;
    __nv_bfloat16 *vt_h, *vt_l;
    cudaGetSymbolAddress((void**)&qkv, g_qkv);
    cudaGetSymbolAddress((void**)&attn, g_attn);
    cudaGetSymbolAddress((void**)&hid_h, g_hid_h);
    cudaGetSymbolAddress((void**)&hid_l, g_hid_l);
    cudaGetSymbolAddress((void**)&attn_h, g_attn_h);
    cudaGetSymbolAddress((void**)&attn_l, g_attn_l);
    cudaGetSymbolAddress((void**)&wqkv_h, g_wqkv_h);
    cudaGetSymbolAddress((void**)&wqkv_l, g_wqkv_l);
    cudaGetSymbolAddress((void**)&wo_h, g_wo_h);
    cudaGetSymbolAddress((void**)&wo_l, g_wo_l);
    cudaGetSymbolAddress((void**)&qkvb_h, g_qkvb_h);
    cudaGetSymbolAddress((void**)&qkvb_l, g_qkvb_l);
    cudaGetSymbolAddress((void**)&vt_h, g_vt_h);
    cudaGetSymbolAddress((void**)&vt_l, g_vt_l);

    cudaFuncSetAttribute(gemm3x_kernel,
                         cudaFuncAttributeMaxDynamicSharedMemorySize, GEMM_SMEM);
    cudaFuncSetAttribute(attn_mma_kernel,
                         cudaFuncAttributeMaxDynamicSharedMemorySize, ATTN2_SMEM);

    // 0) weight + hidden pre-split
    {
        dim3 g1(QKVN / 32, HID_ / 32);
        split_wT_kernel<<<g1, 256>>>(wqkv, wqkv_h, wqkv_l, HID_, QKVN);
        dim3 g2(HID_ / 32, HID_ / 32);
        split_wT_kernel<<<g2, 256>>>(wo, wo_h, wo_l, HID_, HID_);
        size_t n4 = (size_t)TOK * HID_ / 4;
        split_a_kernel<<<(unsigned)((n4 + 255) / 256), 256>>>(hidden, hid_h, hid_l, n4);
    }
    // 1) QKV projection
    {
        dim3 grid(QKVN / 128, TOK / 128);  // (24, 64)
        gemm3x_kernel<<<grid, 256, GEMM_SMEM>>>(hid_h, hid_l, wqkv_h, wqkv_l,
                                                bqkv, qkv, TOK, QKVN, HID_);
    }
    // 2) RoPE + split (q,k) and V transpose + split
    {
        int total = TOK * 1280;
        rope_split_kernel<<<total / 256, 256>>>(qkv, cosb, sinb, qkvb_h, qkvb_l);
        dim3 gv(S_ / 32, HD_ / 32, B_ * NKV_);
        vsplitT_kernel<<<gv, 256>>>(qkv, vt_h, vt_l);
    }
    // 3) Attention
    {
        dim3 grid(S_ / 128, NH_, B_);  // (16, 16, 4)
        attn_mma_kernel<<<grid, 256, ATTN2_SMEM>>>(qkvb_h, qkvb_l, vt_h, vt_l, attn);
    }
    // 3.5) split attention output for out-proj A operand
    {
        size_t n4 = (size_t)TOK * HID_ / 4;
        split_a_kernel<<<(unsigned)((n4 + 255) / 256), 256>>>(attn, attn_h, attn_l, n4);
    }
    // 4) Output projection
    {
        dim3 grid(HID_ / 128, TOK / 128);  // (16, 64)
        gemm3x_kernel<<<grid, 256, GEMM_SMEM>>>(attn_h, attn_l, wo_h, wo_l,
                                                bo, out, TOK, HID_, HID_);
    }
}